// round 5
// baseline (speedup 1.0000x reference)
#include <cuda_runtime.h>
#include <math.h>
#include <stdint.h>

#define TSEQ 4096
#define NH   16
#define NKV  4
#define HDIM 64
#define DIM  1024
#define QKVD 1536
#define KVOFF 1024
#define VOFF  1280

// ---------------- scratch (device globals; no cudaMalloc allowed) ----------
__device__ float g_qkv[TSEQ * QKVD];
__device__ float g_q[NH * TSEQ * HDIM];
__device__ float g_k[NKV * TSEQ * HDIM];
__device__ float g_v[NKV * TSEQ * HDIM];
__device__ float g_y[TSEQ * DIM];
__device__ float g_xr[TSEQ * DIM];       // pre-rounded copies (tf32-in-f32)
__device__ float g_wq[QKVD * DIM];
__device__ float g_wp[DIM * DIM];

// ---------------- tf32 helpers ---------------------------------------------
__device__ __forceinline__ uint32_t f2tf(float f) {
    uint32_t u;
    asm("cvt.rna.tf32.f32 %0, %1;" : "=r"(u) : "f"(f));
    return u;
}

__device__ __forceinline__ float ex2(float x) {
    float r;
    asm("ex2.approx.f32 %0, %1;" : "=f"(r) : "f"(x));
    return r;
}

__device__ __forceinline__ void mma_tf32(float c[4], const uint32_t a[4],
                                         const uint32_t b[2]) {
    asm volatile(
        "mma.sync.aligned.m16n8k8.row.col.f32.tf32.tf32.f32 "
        "{%0,%1,%2,%3}, {%4,%5,%6,%7}, {%8,%9}, {%0,%1,%2,%3};"
        : "+f"(c[0]), "+f"(c[1]), "+f"(c[2]), "+f"(c[3])
        : "r"(a[0]), "r"(a[1]), "r"(a[2]), "r"(a[3]), "r"(b[0]), "r"(b[1]));
}

__device__ __forceinline__ void cp16(void* smem_dst, const void* gsrc) {
    uint32_t s = (uint32_t)__cvta_generic_to_shared(smem_dst);
    asm volatile("cp.async.ca.shared.global [%0], [%1], 16;" :: "r"(s), "l"(gsrc));
}

// ---------------- fused pre-round pass: f32 -> tf32-rounded f32 ------------
__global__ __launch_bounds__(256) void round3_kernel(
    const float* __restrict__ a, float* __restrict__ da, int n1,
    const float* __restrict__ b, float* __restrict__ db, int n2,
    const float* __restrict__ c, float* __restrict__ dc, int n3) {
    int i = blockIdx.x * blockDim.x + threadIdx.x;
    int total = n1 + n2 + n3;
    for (; i < total; i += gridDim.x * blockDim.x) {
        const float* s;
        float* d;
        int j = i;
        if (j < n1) { s = a; d = da; }
        else if (j < n1 + n2) { j -= n1; s = b; d = db; }
        else { j -= n1 + n2; s = c; d = dc; }
        float4 v = ((const float4*)s)[j];
        uint4 u = make_uint4(f2tf(v.x), f2tf(v.y), f2tf(v.z), f2tf(v.w));
        ((uint4*)d)[j] = u;
    }
}

// ---------------- tf32 GEMM: C[M,N] = A[M,K] * B[N,K]^T --------------------
// inputs pre-rounded. 128x128 tile, 8 warps (2m x 4n), warp tile 64x32.
// k-step 32, 3-stage cp.async pipeline. smem [row][k] stride 36 u32.
#define GS 36
#define GSTG (128 * GS)          // per-tensor per-stage u32
#define GEMM_SMEM_BYTES (3 * 2 * GSTG * 4)

__global__ __launch_bounds__(256, 2) void gemm_tf32(const float* __restrict__ A,
                                                    const float* __restrict__ B,
                                                    float* __restrict__ C,
                                                    int M, int N, int K) {
    extern __shared__ __align__(16) uint32_t gsm[];
    const int tid = threadIdx.x;
    const int m0 = blockIdx.y * 128;
    const int n0 = blockIdx.x * 128;
    const int warp = tid >> 5;
    const int lane = tid & 31;
    const int gid = lane >> 2;
    const int tig = lane & 3;
    const int wm = (warp & 1) * 64;
    const int wn = (warp >> 1) * 32;

    auto issue = [&](int it) {
        int k0 = it * 32;
        uint32_t* As = gsm + (it % 3) * 2 * GSTG;
        uint32_t* Bs = As + GSTG;
#pragma unroll
        for (int i = 0; i < 8; i++) {
            int id = tid + 256 * i;       // 0..2047
            int rid = id & 1023;
            int row = rid >> 3, c4 = (rid & 7) << 2;
            const float* src = (id < 1024)
                ? A + (size_t)(m0 + row) * K + k0 + c4
                : B + (size_t)(n0 + row) * K + k0 + c4;
            uint32_t* dst = ((id < 1024) ? As : Bs) + row * GS + c4;
            cp16(dst, src);
        }
        asm volatile("cp.async.commit_group;");
    };

    float acc[4][4][4];
#pragma unroll
    for (int mi = 0; mi < 4; mi++)
#pragma unroll
        for (int ni = 0; ni < 4; ni++)
#pragma unroll
            for (int f = 0; f < 4; f++) acc[mi][ni][f] = 0.f;

    const int nIter = K / 32;
    issue(0);
    issue(1);

    for (int it = 0; it < nIter; it++) {
        asm volatile("cp.async.wait_group 1;");
        __syncthreads();
        if (it + 2 < nIter) issue(it + 2);
        else asm volatile("cp.async.commit_group;");

        const uint32_t* As = gsm + (it % 3) * 2 * GSTG;
        const uint32_t* Bs = As + GSTG;
#pragma unroll
        for (int ks = 0; ks < 32; ks += 8) {
            uint32_t af[4][4], bf[4][2];
#pragma unroll
            for (int mi = 0; mi < 4; mi++) {
                int r = (wm + 16 * mi + gid) * GS + ks + tig;
                af[mi][0] = As[r];
                af[mi][1] = As[r + 8 * GS];
                af[mi][2] = As[r + 4];
                af[mi][3] = As[r + 8 * GS + 4];
            }
#pragma unroll
            for (int ni = 0; ni < 4; ni++) {
                int r = (wn + 8 * ni + gid) * GS + ks + tig;
                bf[ni][0] = Bs[r];
                bf[ni][1] = Bs[r + 4];
            }
#pragma unroll
            for (int mi = 0; mi < 4; mi++)
#pragma unroll
                for (int ni = 0; ni < 4; ni++) mma_tf32(acc[mi][ni], af[mi], bf[ni]);
        }
    }

#pragma unroll
    for (int mi = 0; mi < 4; mi++) {
        int r0 = m0 + wm + 16 * mi + gid;
#pragma unroll
        for (int ni = 0; ni < 4; ni++) {
            int c = n0 + wn + 8 * ni + 2 * tig;
            *(float2*)(C + (size_t)r0 * N + c) = make_float2(acc[mi][ni][0], acc[mi][ni][1]);
            *(float2*)(C + (size_t)(r0 + 8) * N + c) = make_float2(acc[mi][ni][2], acc[mi][ni][3]);
        }
    }
}

// ---------------- prep: RMSNorm + RoPE + gain, outputs tf32-rounded --------
__global__ __launch_bounds__(256) void prep_kernel(const float* __restrict__ qkv,
                                                   const float* __restrict__ gain) {
    const int warp = blockIdx.x * 8 + (threadIdx.x >> 5);
    const int lane = threadIdx.x & 31;
    const int NQ = TSEQ * NH;
    const int NK = TSEQ * NKV;
    if (warp >= NQ + 2 * NK) return;

    if (warp < NQ + NK) {
        int t, off;
        float g;
        float* dst;
        if (warp < NQ) {
            t = warp / NH;
            int h = warp % NH;
            off = h * HDIM;
            g = gain[h];
            dst = g_q + ((size_t)h * TSEQ + t) * HDIM;
        } else {
            int w = warp - NQ;
            t = w / NKV;
            int kv = w % NKV;
            off = KVOFF + kv * HDIM;
            g = 1.0f;
            dst = g_k + ((size_t)kv * TSEQ + t) * HDIM;
        }
        const float* src = qkv + (size_t)t * QKVD + off;
        float x1 = src[lane], x2 = src[lane + 32];
        float ss = x1 * x1 + x2 * x2;
        ss += __shfl_xor_sync(0xffffffffu, ss, 16);
        ss += __shfl_xor_sync(0xffffffffu, ss, 8);
        ss += __shfl_xor_sync(0xffffffffu, ss, 4);
        ss += __shfl_xor_sync(0xffffffffu, ss, 2);
        ss += __shfl_xor_sync(0xffffffffu, ss, 1);
        float r = rsqrtf(ss * (1.0f / 64.0f) + 1.1920929e-07f);
        x1 *= r; x2 *= r;
        float invf = (float)(1.0 / pow(10000.0, (double)lane * (1.0 / 32.0)));
        float fr = (float)t * invf;
        float s, c;
        sincosf(fr, &s, &c);
        dst[lane]      = __uint_as_float(f2tf((x1 * c + x2 * s) * g));
        dst[lane + 32] = __uint_as_float(f2tf((x2 * c - x1 * s) * g));
    } else {
        int w = warp - NQ - NK;
        int t = w / NKV, kv = w % NKV;
        const float* src = qkv + (size_t)t * QKVD + VOFF + kv * HDIM;
        float* dst = g_v + ((size_t)kv * TSEQ + t) * HDIM;
        dst[lane] = __uint_as_float(f2tf(src[lane]));
        dst[lane + 32] = __uint_as_float(f2tf(src[lane + 32]));
    }
}

// ---------------- flash attention: 128-row Q tile, 8 warps -----------------
// Q fragments in registers; K/V double-buffered cp.async; P in own region.
// m/l tracked in log2 domain (S pre-scaled by scale*log2e).
#define KSR 68
#define VSR 72
#define ATTN_SMEM_U32 (2 * 64 * KSR + 2 * 64 * VSR + 128 * KSR)
#define ATTN_SMEM_BYTES (ATTN_SMEM_U32 * 4)

__global__ __launch_bounds__(256, 2) void attn_kernel() {
    extern __shared__ __align__(16) uint32_t smu[];
    uint32_t* Kb = smu;                           // [2][64][68]
    uint32_t* Vb = smu + 2 * 64 * KSR;            // [2][64][72]
    uint32_t* Ps = smu + 2 * 64 * KSR + 2 * 64 * VSR;  // [128][68]

    const int tid = threadIdx.x;
    const int h = blockIdx.y;
    const int qb = (int)gridDim.x - 1 - (int)blockIdx.x;  // heavy CTAs first
    const int kvh = h >> 2;
    const int lane = tid & 31;
    const int warp = tid >> 5;
    const int gid = lane >> 2;
    const int tig = lane & 3;
    const int q0w = warp * 16;
    const int kbmax = 2 * qb + 1;

    const float* kbase = g_k + ((size_t)kvh * TSEQ) * HDIM;
    const float* vbase = g_v + ((size_t)kvh * TSEQ) * HDIM;

    auto issueKV = [&](int kb) {
        const float* kp = kbase + (size_t)kb * 64 * HDIM;
        const float* vp = vbase + (size_t)kb * 64 * HDIM;
        uint32_t* Kd = Kb + (kb & 1) * 64 * KSR;
        uint32_t* Vd = Vb + (kb & 1) * 64 * VSR;
#pragma unroll
        for (int i = 0; i < 4; i++) {
            int slot = tid + 256 * i;       // 0..1023 = 64 rows x 16 chunks
            int row = slot >> 4, c4 = (slot & 15) << 2;
            cp16(Kd + row * KSR + c4, kp + row * HDIM + c4);
            cp16(Vd + row * VSR + c4, vp + row * HDIM + c4);
        }
        asm volatile("cp.async.commit_group;");
    };

    issueKV(0);

    // ---- stage Q tile through Ps (coalesced), then frags -> registers ----
    {
        const float* qp = g_q + ((size_t)h * TSEQ + (size_t)qb * 128) * HDIM;
#pragma unroll
        for (int i = 0; i < 8; i++) {
            int slot = tid + 256 * i;       // 0..2047 = 128 rows x 16 chunks
            int row = slot >> 4, c4 = (slot & 15) << 2;
            *(float4*)&Ps[row * KSR + c4] = *(const float4*)(qp + row * HDIM + c4);
        }
    }
    __syncthreads();
    uint32_t Qf[8][4];
#pragma unroll
    for (int ks = 0; ks < 8; ks++) {
        int r = (q0w + gid) * KSR + 8 * ks + tig;
        Qf[ks][0] = Ps[r];
        Qf[ks][1] = Ps[r + 8 * KSR];
        Qf[ks][2] = Ps[r + 4];
        Qf[ks][3] = Ps[r + 8 * KSR + 4];
    }

    float of[8][4];
    float m0 = -INFINITY, m1 = -INFINITY, l0 = 0.f, l1 = 0.f;
#pragma unroll
    for (int ni = 0; ni < 8; ni++)
#pragma unroll
        for (int f = 0; f < 4; f++) of[ni][f] = 0.f;

    const float cs = 0.18033688011112042f;  // (1/8) * log2(e)
    const int r0g = qb * 128 + q0w + gid;
    const int r1g = r0g + 8;

    for (int kb = 0; kb <= kbmax; kb++) {
        asm volatile("cp.async.wait_group 0;");
        __syncthreads();   // KV[cur] visible to all; prev iter fully done
        if (kb < kbmax) issueKV(kb + 1);

        const uint32_t* Kc = Kb + (kb & 1) * 64 * KSR;
        const uint32_t* Vc = Vb + (kb & 1) * 64 * VSR;

        // ---- S = Q K^T ----
        float sf[8][4];
#pragma unroll
        for (int ni = 0; ni < 8; ni++)
#pragma unroll
            for (int f = 0; f < 4; f++) sf[ni][f] = 0.f;

#pragma unroll
        for (int ks = 0; ks < 8; ks++) {
#pragma unroll
            for (int ni = 0; ni < 8; ni++) {
                uint32_t b[2];
                int r = (8 * ni + gid) * KSR + 8 * ks + tig;
                b[0] = Kc[r];
                b[1] = Kc[r + 4];
                mma_tf32(sf[ni], Qf[ks], b);
            }
        }

        // ---- scale*log2e + causal mask ----
        if (kb >= 2 * qb) {
#pragma unroll
            for (int ni = 0; ni < 8; ni++) {
                int c0 = kb * 64 + 8 * ni + 2 * tig, c1 = c0 + 1;
                sf[ni][0] = (c0 <= r0g) ? sf[ni][0] * cs : -INFINITY;
                sf[ni][1] = (c1 <= r0g) ? sf[ni][1] * cs : -INFINITY;
                sf[ni][2] = (c0 <= r1g) ? sf[ni][2] * cs : -INFINITY;
                sf[ni][3] = (c1 <= r1g) ? sf[ni][3] * cs : -INFINITY;
            }
        } else {
#pragma unroll
            for (int ni = 0; ni < 8; ni++)
#pragma unroll
                for (int f = 0; f < 4; f++) sf[ni][f] *= cs;
        }

        // ---- online softmax in log2 domain ----
        float mx0 = -INFINITY, mx1 = -INFINITY;
#pragma unroll
        for (int ni = 0; ni < 8; ni++) {
            mx0 = fmaxf(mx0, fmaxf(sf[ni][0], sf[ni][1]));
            mx1 = fmaxf(mx1, fmaxf(sf[ni][2], sf[ni][3]));
        }
        mx0 = fmaxf(mx0, __shfl_xor_sync(0xffffffffu, mx0, 1));
        mx0 = fmaxf(mx0, __shfl_xor_sync(0xffffffffu, mx0, 2));
        mx1 = fmaxf(mx1, __shfl_xor_sync(0xffffffffu, mx1, 1));
        mx1 = fmaxf(mx1, __shfl_xor_sync(0xffffffffu, mx1, 2));
        float mn0 = fmaxf(m0, mx0), mn1 = fmaxf(m1, mx1);
        float alpha0 = ex2(m0 - mn0), alpha1 = ex2(m1 - mn1);
        m0 = mn0; m1 = mn1;

        // exp + progressive P store (frees sf registers early)
        float s0 = 0.f, s1 = 0.f;
#pragma unroll
        for (int ni = 0; ni < 8; ni++) {
            float p0 = ex2(sf[ni][0] - mn0);
            float p1 = ex2(sf[ni][1] - mn0);
            float p2 = ex2(sf[ni][2] - mn1);
            float p3 = ex2(sf[ni][3] - mn1);
            s0 += p0 + p1;
            s1 += p2 + p3;
            int c = 8 * ni + 2 * tig;
            *(uint2*)&Ps[(q0w + gid) * KSR + c] = make_uint2(f2tf(p0), f2tf(p1));
            *(uint2*)&Ps[(q0w + gid + 8) * KSR + c] = make_uint2(f2tf(p2), f2tf(p3));
        }
        s0 += __shfl_xor_sync(0xffffffffu, s0, 1);
        s0 += __shfl_xor_sync(0xffffffffu, s0, 2);
        s1 += __shfl_xor_sync(0xffffffffu, s1, 1);
        s1 += __shfl_xor_sync(0xffffffffu, s1, 2);
        l0 = l0 * alpha0 + s0;
        l1 = l1 * alpha1 + s1;
#pragma unroll
        for (int ni = 0; ni < 8; ni++) {
            of[ni][0] *= alpha0; of[ni][1] *= alpha0;
            of[ni][2] *= alpha1; of[ni][3] *= alpha1;
        }
        __syncwarp();   // P rows are warp-private

        // ---- O += P V ----
#pragma unroll
        for (int ks = 0; ks < 8; ks++) {
            uint32_t a[4];
            int r = (q0w + gid) * KSR + 8 * ks + tig;
            a[0] = Ps[r];
            a[1] = Ps[r + 8 * KSR];
            a[2] = Ps[r + 4];
            a[3] = Ps[r + 8 * KSR + 4];
#pragma unroll
            for (int ni = 0; ni < 8; ni++) {
                uint32_t b[2];
                int rv = (8 * ks + tig) * VSR + 8 * ni + gid;
                b[0] = Vc[rv];
                b[1] = Vc[rv + 4 * VSR];
                mma_tf32(of[ni], a, b);
            }
        }
    }

    // ---- epilogue: normalize, store y pre-rounded to tf32 ----
    float inv0 = 1.0f / l0, inv1 = 1.0f / l1;
    float* ybase = g_y + (size_t)(qb * 128 + q0w + gid) * DIM + h * HDIM;
#pragma unroll
    for (int ni = 0; ni < 8; ni++) {
        int c = 8 * ni + 2 * tig;
        *(uint2*)(ybase + c) =
            make_uint2(f2tf(of[ni][0] * inv0), f2tf(of[ni][1] * inv0));
        *(uint2*)(ybase + 8 * DIM + c) =
            make_uint2(f2tf(of[ni][2] * inv1), f2tf(of[ni][3] * inv1));
    }
}

// ---------------- launch ---------------------------------------------------
extern "C" void kernel_launch(void* const* d_in, const int* in_sizes, int n_in,
                              void* d_out, int out_size) {
    const float* x      = (const float*)d_in[0];
    const float* w_qkv  = (const float*)d_in[1];
    const float* w_proj = (const float*)d_in[2];
    const float* q_gain = (const float*)d_in[3];
    float* out = (float*)d_out;

    float *qkv_p, *y_p, *xr_p, *wq_p, *wp_p;
    cudaGetSymbolAddress((void**)&qkv_p, g_qkv);
    cudaGetSymbolAddress((void**)&y_p, g_y);
    cudaGetSymbolAddress((void**)&xr_p, g_xr);
    cudaGetSymbolAddress((void**)&wq_p, g_wq);
    cudaGetSymbolAddress((void**)&wp_p, g_wp);

    // fused pre-round of x, w_qkv, w_proj (single launch)
    round3_kernel<<<1024, 256>>>(x, xr_p, TSEQ * DIM / 4,
                                 w_qkv, wq_p, QKVD * DIM / 4,
                                 w_proj, wp_p, DIM * DIM / 4);

    cudaFuncSetAttribute(gemm_tf32, cudaFuncAttributeMaxDynamicSharedMemorySize,
                         GEMM_SMEM_BYTES);
    gemm_tf32<<<dim3(QKVD / 128, TSEQ / 128), 256, GEMM_SMEM_BYTES>>>(
        xr_p, wq_p, qkv_p, TSEQ, QKVD, DIM);

    {
        int nwarps = TSEQ * (NH + 2 * NKV);
        prep_kernel<<<nwarps / 8, 256>>>(qkv_p, q_gain);
    }

    cudaFuncSetAttribute(attn_kernel, cudaFuncAttributeMaxDynamicSharedMemorySize,
                         ATTN_SMEM_BYTES);
    attn_kernel<<<dim3(TSEQ / 128, NH), 256, ATTN_SMEM_BYTES>>>();

    gemm_tf32<<<dim3(DIM / 128, TSEQ / 128), 256, GEMM_SMEM_BYTES>>>(
        y_p, wp_p, out, TSEQ, DIM, DIM);
}

// round 6
// speedup vs baseline: 1.8161x; 1.8161x over previous
#include <cuda_runtime.h>
#include <math.h>
#include <stdint.h>

#define TSEQ 4096
#define NH   16
#define NKV  4
#define HDIM 64
#define DIM  1024
#define QKVD 1536
#define KVOFF 1024
#define VOFF  1280

// ---------------- scratch (device globals; no cudaMalloc allowed) ----------
__device__ float g_qkv[TSEQ * QKVD];
__device__ float g_q[NH * TSEQ * HDIM];
__device__ float g_k[NKV * TSEQ * HDIM];
__device__ float g_v[NKV * TSEQ * HDIM];
__device__ float g_y[TSEQ * DIM];
__device__ float g_xr[TSEQ * DIM];       // pre-rounded copies (tf32-in-f32)
__device__ float g_wq[QKVD * DIM];
__device__ float g_wp[DIM * DIM];

// ---------------- tf32 helpers ---------------------------------------------
__device__ __forceinline__ uint32_t f2tf(float f) {
    uint32_t u;
    asm("cvt.rna.tf32.f32 %0, %1;" : "=r"(u) : "f"(f));
    return u;
}

__device__ __forceinline__ float ex2(float x) {
    float r;
    asm("ex2.approx.f32 %0, %1;" : "=f"(r) : "f"(x));
    return r;
}

__device__ __forceinline__ void mma_tf32(float c[4], const uint32_t a[4],
                                         const uint32_t b[2]) {
    asm volatile(
        "mma.sync.aligned.m16n8k8.row.col.f32.tf32.tf32.f32 "
        "{%0,%1,%2,%3}, {%4,%5,%6,%7}, {%8,%9}, {%0,%1,%2,%3};"
        : "+f"(c[0]), "+f"(c[1]), "+f"(c[2]), "+f"(c[3])
        : "r"(a[0]), "r"(a[1]), "r"(a[2]), "r"(a[3]), "r"(b[0]), "r"(b[1]));
}

__device__ __forceinline__ void cp16(void* smem_dst, const void* gsrc) {
    uint32_t s = (uint32_t)__cvta_generic_to_shared(smem_dst);
    asm volatile("cp.async.ca.shared.global [%0], [%1], 16;" :: "r"(s), "l"(gsrc));
}

// ---------------- fused pre-round pass: f32 -> tf32-rounded f32 ------------
__global__ __launch_bounds__(256) void round3_kernel(
    const float* __restrict__ a, float* __restrict__ da, int n1,
    const float* __restrict__ b, float* __restrict__ db, int n2,
    const float* __restrict__ c, float* __restrict__ dc, int n3) {
    int i = blockIdx.x * blockDim.x + threadIdx.x;
    int total = n1 + n2 + n3;
    for (; i < total; i += gridDim.x * blockDim.x) {
        const float* s;
        float* d;
        int j = i;
        if (j < n1) { s = a; d = da; }
        else if (j < n1 + n2) { j -= n1; s = b; d = db; }
        else { j -= n1 + n2; s = c; d = dc; }
        float4 v = ((const float4*)s)[j];
        uint4 u = make_uint4(f2tf(v.x), f2tf(v.y), f2tf(v.z), f2tf(v.w));
        ((uint4*)d)[j] = u;
    }
}

// ---------------- tf32 GEMM (known-good R2 config): C = A * B^T ------------
// 128x128 tile, 8 warps (2m x 4n), warp tile 64x32, k-step 16,
// 3-stage cp.async pipeline, smem row stride 20 u32 (conflict-free frags).
#define GS 20
#define GSTG (128 * GS)          // per-tensor per-stage u32
#define GEMM_SMEM_BYTES (3 * 2 * GSTG * 4)

__global__ __launch_bounds__(256, 2) void gemm_tf32(const float* __restrict__ A,
                                                    const float* __restrict__ B,
                                                    float* __restrict__ C,
                                                    int M, int N, int K) {
    extern __shared__ __align__(16) uint32_t gsm[];
    const int tid = threadIdx.x;
    const int m0 = blockIdx.y * 128;
    const int n0 = blockIdx.x * 128;
    const int warp = tid >> 5;
    const int lane = tid & 31;
    const int gid = lane >> 2;
    const int tig = lane & 3;
    const int wm = (warp & 1) * 64;
    const int wn = (warp >> 1) * 32;

    auto issue = [&](int k0, int s) {
        uint32_t* As = gsm + s * 2 * GSTG;
        uint32_t* Bs = As + GSTG;
#pragma unroll
        for (int i = 0; i < 4; i++) {
            int id = tid + 256 * i;       // 0..1023
            int rid = id & 511;
            int row = rid >> 2, c4 = (rid & 3) << 2;
            const float* src = (id < 512)
                ? A + (size_t)(m0 + row) * K + k0 + c4
                : B + (size_t)(n0 + row) * K + k0 + c4;
            uint32_t* dst = ((id < 512) ? As : Bs) + row * GS + c4;
            cp16(dst, src);
        }
        asm volatile("cp.async.commit_group;");
    };

    float acc[4][4][4];
#pragma unroll
    for (int mi = 0; mi < 4; mi++)
#pragma unroll
        for (int ni = 0; ni < 4; ni++)
#pragma unroll
            for (int f = 0; f < 4; f++) acc[mi][ni][f] = 0.f;

    const int nIter = K / 16;
    issue(0, 0);
    issue(16, 1);

    for (int it = 0; it < nIter; it++) {
        asm volatile("cp.async.wait_group 1;");
        __syncthreads();
        if (it + 2 < nIter) issue((it + 2) * 16, (it + 2) % 3);
        else asm volatile("cp.async.commit_group;");

        const uint32_t* As = gsm + (it % 3) * 2 * GSTG;
        const uint32_t* Bs = As + GSTG;
#pragma unroll
        for (int ks = 0; ks < 16; ks += 8) {
            uint32_t af[4][4], bf[4][2];
#pragma unroll
            for (int mi = 0; mi < 4; mi++) {
                int r = (wm + 16 * mi + gid) * GS + ks + tig;
                af[mi][0] = As[r];
                af[mi][1] = As[r + 8 * GS];
                af[mi][2] = As[r + 4];
                af[mi][3] = As[r + 8 * GS + 4];
            }
#pragma unroll
            for (int ni = 0; ni < 4; ni++) {
                int r = (wn + 8 * ni + gid) * GS + ks + tig;
                bf[ni][0] = Bs[r];
                bf[ni][1] = Bs[r + 4];
            }
#pragma unroll
            for (int mi = 0; mi < 4; mi++)
#pragma unroll
                for (int ni = 0; ni < 4; ni++) mma_tf32(acc[mi][ni], af[mi], bf[ni]);
        }
    }

#pragma unroll
    for (int mi = 0; mi < 4; mi++) {
        int r0 = m0 + wm + 16 * mi + gid;
#pragma unroll
        for (int ni = 0; ni < 4; ni++) {
            int c = n0 + wn + 8 * ni + 2 * tig;
            *(float2*)(C + (size_t)r0 * N + c) = make_float2(acc[mi][ni][0], acc[mi][ni][1]);
            *(float2*)(C + (size_t)(r0 + 8) * N + c) = make_float2(acc[mi][ni][2], acc[mi][ni][3]);
        }
    }
}

// ---------------- prep: RMSNorm + RoPE + gain, outputs tf32-rounded --------
__global__ __launch_bounds__(256) void prep_kernel(const float* __restrict__ qkv,
                                                   const float* __restrict__ gain) {
    const int warp = blockIdx.x * 8 + (threadIdx.x >> 5);
    const int lane = threadIdx.x & 31;
    const int NQ = TSEQ * NH;
    const int NK = TSEQ * NKV;
    if (warp >= NQ + 2 * NK) return;

    if (warp < NQ + NK) {
        int t, off;
        float g;
        float* dst;
        if (warp < NQ) {
            t = warp / NH;
            int h = warp % NH;
            off = h * HDIM;
            g = gain[h];
            dst = g_q + ((size_t)h * TSEQ + t) * HDIM;
        } else {
            int w = warp - NQ;
            t = w / NKV;
            int kv = w % NKV;
            off = KVOFF + kv * HDIM;
            g = 1.0f;
            dst = g_k + ((size_t)kv * TSEQ + t) * HDIM;
        }
        const float* src = qkv + (size_t)t * QKVD + off;
        float x1 = src[lane], x2 = src[lane + 32];
        float ss = x1 * x1 + x2 * x2;
        ss += __shfl_xor_sync(0xffffffffu, ss, 16);
        ss += __shfl_xor_sync(0xffffffffu, ss, 8);
        ss += __shfl_xor_sync(0xffffffffu, ss, 4);
        ss += __shfl_xor_sync(0xffffffffu, ss, 2);
        ss += __shfl_xor_sync(0xffffffffu, ss, 1);
        float r = rsqrtf(ss * (1.0f / 64.0f) + 1.1920929e-07f);
        x1 *= r; x2 *= r;
        float invf = (float)(1.0 / pow(10000.0, (double)lane * (1.0 / 32.0)));
        float fr = (float)t * invf;
        float s, c;
        sincosf(fr, &s, &c);
        dst[lane]      = __uint_as_float(f2tf((x1 * c + x2 * s) * g));
        dst[lane + 32] = __uint_as_float(f2tf((x2 * c - x1 * s) * g));
    } else {
        int w = warp - NQ - NK;
        int t = w / NKV, kv = w % NKV;
        const float* src = qkv + (size_t)t * QKVD + VOFF + kv * HDIM;
        float* dst = g_v + ((size_t)kv * TSEQ + t) * HDIM;
        dst[lane] = __uint_as_float(f2tf(src[lane]));
        dst[lane + 32] = __uint_as_float(f2tf(src[lane + 32]));
    }
}

// ---------------- flash attention: 128-row Q tile, 8 warps -----------------
// Q fragments in registers; K/V double-buffered cp.async.
// P NEVER touches smem: S-accumulator regs are fed directly into the PV mma
// as the A-fragment ({c0,c2,c1,c3}), with V b-fragments loaded from permuted
// rows (8ks+2*tig, 8ks+2*tig+1) — PV is invariant under the shared k-perm.
#define KSR 68
#define VSR 68
#define ATTN_SMEM_U32 (2 * 64 * KSR + 2 * 64 * VSR)
#define ATTN_SMEM_BYTES (ATTN_SMEM_U32 * 4)

__global__ __launch_bounds__(256, 2) void attn_kernel() {
    extern __shared__ __align__(16) uint32_t smu[];
    uint32_t* Kb = smu;                    // [2][64][68]
    uint32_t* Vb = smu + 2 * 64 * KSR;     // [2][64][68]

    const int tid = threadIdx.x;
    const int h = blockIdx.y;
    const int qb = (int)gridDim.x - 1 - (int)blockIdx.x;  // heavy CTAs first
    const int kvh = h >> 2;
    const int lane = tid & 31;
    const int warp = tid >> 5;
    const int gid = lane >> 2;
    const int tig = lane & 3;
    const int q0w = warp * 16;
    const int kbmax = 2 * qb + 1;

    const float* kbase = g_k + ((size_t)kvh * TSEQ) * HDIM;
    const float* vbase = g_v + ((size_t)kvh * TSEQ) * HDIM;

    auto issueKV = [&](int kb) {
        const float* kp = kbase + (size_t)kb * 64 * HDIM;
        const float* vp = vbase + (size_t)kb * 64 * HDIM;
        uint32_t* Kd = Kb + (kb & 1) * 64 * KSR;
        uint32_t* Vd = Vb + (kb & 1) * 64 * VSR;
#pragma unroll
        for (int i = 0; i < 4; i++) {
            int slot = tid + 256 * i;       // 0..1023 = 64 rows x 16 chunks
            int row = slot >> 4, c4 = (slot & 15) << 2;
            cp16(Kd + row * KSR + c4, kp + row * HDIM + c4);
            cp16(Vd + row * VSR + c4, vp + row * HDIM + c4);
        }
        asm volatile("cp.async.commit_group;");
    };

    // ---- stage Q tile through the K/V smem area, then frags -> registers ----
    {
        const float* qp = g_q + ((size_t)h * TSEQ + (size_t)qb * 128) * HDIM;
#pragma unroll
        for (int i = 0; i < 8; i++) {
            int slot = tid + 256 * i;       // 0..2047 = 128 rows x 16 chunks
            int row = slot >> 4, c4 = (slot & 15) << 2;
            *(float4*)&smu[row * KSR + c4] = *(const float4*)(qp + row * HDIM + c4);
        }
    }
    __syncthreads();
    uint32_t Qf[8][4];
#pragma unroll
    for (int ks = 0; ks < 8; ks++) {
        int r = (q0w + gid) * KSR + 8 * ks + tig;
        Qf[ks][0] = smu[r];
        Qf[ks][1] = smu[r + 8 * KSR];
        Qf[ks][2] = smu[r + 4];
        Qf[ks][3] = smu[r + 8 * KSR + 4];
    }
    __syncthreads();   // Q frags read; smem now free for K/V

    issueKV(0);

    float of[8][4];
    float m0 = -INFINITY, m1 = -INFINITY, l0 = 0.f, l1 = 0.f;
#pragma unroll
    for (int ni = 0; ni < 8; ni++)
#pragma unroll
        for (int f = 0; f < 4; f++) of[ni][f] = 0.f;

    const float cs = 0.18033688011112042f;  // (1/8) * log2(e)
    const int r0g = qb * 128 + q0w + gid;
    const int r1g = r0g + 8;

    for (int kb = 0; kb <= kbmax; kb++) {
        asm volatile("cp.async.wait_group 0;");
        __syncthreads();   // KV[cur] visible to all; prev iter fully done
        if (kb < kbmax) issueKV(kb + 1);

        const uint32_t* Kc = Kb + (kb & 1) * 64 * KSR;
        const uint32_t* Vc = Vb + (kb & 1) * 64 * VSR;

        // ---- S = Q K^T ----
        float sf[8][4];
#pragma unroll
        for (int ni = 0; ni < 8; ni++)
#pragma unroll
            for (int f = 0; f < 4; f++) sf[ni][f] = 0.f;

#pragma unroll
        for (int ks = 0; ks < 8; ks++) {
#pragma unroll
            for (int ni = 0; ni < 8; ni++) {
                uint32_t b[2];
                int r = (8 * ni + gid) * KSR + 8 * ks + tig;
                b[0] = Kc[r];
                b[1] = Kc[r + 4];
                mma_tf32(sf[ni], Qf[ks], b);
            }
        }

        // ---- scale*log2e + causal mask ----
        if (kb >= 2 * qb) {
#pragma unroll
            for (int ni = 0; ni < 8; ni++) {
                int c0 = kb * 64 + 8 * ni + 2 * tig, c1 = c0 + 1;
                sf[ni][0] = (c0 <= r0g) ? sf[ni][0] * cs : -INFINITY;
                sf[ni][1] = (c1 <= r0g) ? sf[ni][1] * cs : -INFINITY;
                sf[ni][2] = (c0 <= r1g) ? sf[ni][2] * cs : -INFINITY;
                sf[ni][3] = (c1 <= r1g) ? sf[ni][3] * cs : -INFINITY;
            }
        } else {
#pragma unroll
            for (int ni = 0; ni < 8; ni++)
#pragma unroll
                for (int f = 0; f < 4; f++) sf[ni][f] *= cs;
        }

        // ---- online softmax in log2 domain ----
        float mx0 = -INFINITY, mx1 = -INFINITY;
#pragma unroll
        for (int ni = 0; ni < 8; ni++) {
            mx0 = fmaxf(mx0, fmaxf(sf[ni][0], sf[ni][1]));
            mx1 = fmaxf(mx1, fmaxf(sf[ni][2], sf[ni][3]));
        }
        mx0 = fmaxf(mx0, __shfl_xor_sync(0xffffffffu, mx0, 1));
        mx0 = fmaxf(mx0, __shfl_xor_sync(0xffffffffu, mx0, 2));
        mx1 = fmaxf(mx1, __shfl_xor_sync(0xffffffffu, mx1, 1));
        mx1 = fmaxf(mx1, __shfl_xor_sync(0xffffffffu, mx1, 2));
        float mn0 = fmaxf(m0, mx0), mn1 = fmaxf(m1, mx1);
        float alpha0 = ex2(m0 - mn0), alpha1 = ex2(m1 - mn1);
        m0 = mn0; m1 = mn1;

        float s0 = 0.f, s1 = 0.f;
#pragma unroll
        for (int ni = 0; ni < 8; ni++) {
            sf[ni][0] = ex2(sf[ni][0] - mn0);
            sf[ni][1] = ex2(sf[ni][1] - mn0);
            sf[ni][2] = ex2(sf[ni][2] - mn1);
            sf[ni][3] = ex2(sf[ni][3] - mn1);
            s0 += sf[ni][0] + sf[ni][1];
            s1 += sf[ni][2] + sf[ni][3];
        }
        s0 += __shfl_xor_sync(0xffffffffu, s0, 1);
        s0 += __shfl_xor_sync(0xffffffffu, s0, 2);
        s1 += __shfl_xor_sync(0xffffffffu, s1, 1);
        s1 += __shfl_xor_sync(0xffffffffu, s1, 2);
        l0 = l0 * alpha0 + s0;
        l1 = l1 * alpha1 + s1;
#pragma unroll
        for (int ni = 0; ni < 8; ni++) {
            of[ni][0] *= alpha0; of[ni][1] *= alpha0;
            of[ni][2] *= alpha1; of[ni][3] *= alpha1;
        }

        // ---- O += P V  (P straight from registers; V rows permuted) ----
#pragma unroll
        for (int ks = 0; ks < 8; ks++) {
            uint32_t a[4];
            a[0] = f2tf(sf[ks][0]);   // (row gid,   k = 8ks+2tig)
            a[1] = f2tf(sf[ks][2]);   // (row gid+8, k = 8ks+2tig)
            a[2] = f2tf(sf[ks][1]);   // (row gid,   k = 8ks+2tig+1)
            a[3] = f2tf(sf[ks][3]);   // (row gid+8, k = 8ks+2tig+1)
            int rv0 = (8 * ks + 2 * tig) * VSR + gid;
            int rv1 = rv0 + VSR;
#pragma unroll
            for (int ni = 0; ni < 8; ni++) {
                uint32_t b[2];
                b[0] = Vc[rv0 + 8 * ni];
                b[1] = Vc[rv1 + 8 * ni];
                mma_tf32(of[ni], a, b);
            }
        }
    }

    // ---- epilogue: normalize, store y pre-rounded to tf32 ----
    float inv0 = 1.0f / l0, inv1 = 1.0f / l1;
    float* ybase = g_y + (size_t)(qb * 128 + q0w + gid) * DIM + h * HDIM;
#pragma unroll
    for (int ni = 0; ni < 8; ni++) {
        int c = 8 * ni + 2 * tig;
        *(uint2*)(ybase + c) =
            make_uint2(f2tf(of[ni][0] * inv0), f2tf(of[ni][1] * inv0));
        *(uint2*)(ybase + 8 * DIM + c) =
            make_uint2(f2tf(of[ni][2] * inv1), f2tf(of[ni][3] * inv1));
    }
}

// ---------------- launch ---------------------------------------------------
extern "C" void kernel_launch(void* const* d_in, const int* in_sizes, int n_in,
                              void* d_out, int out_size) {
    const float* x      = (const float*)d_in[0];
    const float* w_qkv  = (const float*)d_in[1];
    const float* w_proj = (const float*)d_in[2];
    const float* q_gain = (const float*)d_in[3];
    float* out = (float*)d_out;

    float *qkv_p, *y_p, *xr_p, *wq_p, *wp_p;
    cudaGetSymbolAddress((void**)&qkv_p, g_qkv);
    cudaGetSymbolAddress((void**)&y_p, g_y);
    cudaGetSymbolAddress((void**)&xr_p, g_xr);
    cudaGetSymbolAddress((void**)&wq_p, g_wq);
    cudaGetSymbolAddress((void**)&wp_p, g_wp);

    // fused pre-round of x, w_qkv, w_proj (single launch)
    round3_kernel<<<1024, 256>>>(x, xr_p, TSEQ * DIM / 4,
                                 w_qkv, wq_p, QKVD * DIM / 4,
                                 w_proj, wp_p, DIM * DIM / 4);

    cudaFuncSetAttribute(gemm_tf32, cudaFuncAttributeMaxDynamicSharedMemorySize,
                         GEMM_SMEM_BYTES);
    gemm_tf32<<<dim3(QKVD / 128, TSEQ / 128), 256, GEMM_SMEM_BYTES>>>(
        xr_p, wq_p, qkv_p, TSEQ, QKVD, DIM);

    {
        int nwarps = TSEQ * (NH + 2 * NKV);
        prep_kernel<<<nwarps / 8, 256>>>(qkv_p, q_gain);
    }

    cudaFuncSetAttribute(attn_kernel, cudaFuncAttributeMaxDynamicSharedMemorySize,
                         ATTN_SMEM_BYTES);
    attn_kernel<<<dim3(TSEQ / 128, NH), 256, ATTN_SMEM_BYTES>>>();

    gemm_tf32<<<dim3(DIM / 128, TSEQ / 128), 256, GEMM_SMEM_BYTES>>>(
        y_p, wp_p, out, TSEQ, DIM, DIM);
}

// round 8
// speedup vs baseline: 3.2570x; 1.7934x over previous
#include <cuda_runtime.h>
#include <math.h>
#include <stdint.h>

#define TSEQ 4096
#define NH   16
#define NKV  4
#define HDIM 64
#define DIM  1024
#define QKVD 1536
#define KVOFF 1024
#define VOFF  1280

// ---------------- scratch (device globals; no cudaMalloc allowed) ----------
__device__ float g_qkv[TSEQ * QKVD];
__device__ float g_q[NH * TSEQ * HDIM];
__device__ float g_k[NKV * TSEQ * HDIM];
__device__ float g_v[NKV * TSEQ * HDIM];
__device__ float g_y[TSEQ * DIM];
__device__ float g_xr[TSEQ * DIM];       // pre-rounded copies (tf32-in-f32)
__device__ float g_wq[QKVD * DIM];
__device__ float g_wp[DIM * DIM];
__device__ float g_invf[32];             // rotary inverse frequencies

// ---------------- tf32 helpers ---------------------------------------------
__device__ __forceinline__ uint32_t f2tf(float f) {
    uint32_t u;
    asm("cvt.rna.tf32.f32 %0, %1;" : "=r"(u) : "f"(f));
    return u;
}

__device__ __forceinline__ float ex2(float x) {
    float r;
    asm("ex2.approx.f32 %0, %1;" : "=f"(r) : "f"(x));
    return r;
}

__device__ __forceinline__ void mma_tf32(float c[4], const uint32_t a[4],
                                         const uint32_t b[2]) {
    asm volatile(
        "mma.sync.aligned.m16n8k8.row.col.f32.tf32.tf32.f32 "
        "{%0,%1,%2,%3}, {%4,%5,%6,%7}, {%8,%9}, {%0,%1,%2,%3};"
        : "+f"(c[0]), "+f"(c[1]), "+f"(c[2]), "+f"(c[3])
        : "r"(a[0]), "r"(a[1]), "r"(a[2]), "r"(a[3]), "r"(b[0]), "r"(b[1]));
}

__device__ __forceinline__ void cp16(void* smem_dst, const void* gsrc) {
    uint32_t s = (uint32_t)__cvta_generic_to_shared(smem_dst);
    asm volatile("cp.async.ca.shared.global [%0], [%1], 16;" :: "r"(s), "l"(gsrc));
}

// ---------------- one-shot: inv_freq via double pow (32 threads) -----------
__global__ void freq_kernel() {
    int l = threadIdx.x;
    g_invf[l] = (float)(1.0 / pow(10000.0, (double)l * (1.0 / 32.0)));
}

// ---------------- fused pre-round pass: f32 -> tf32-rounded f32 ------------
__global__ __launch_bounds__(256) void round3_kernel(
    const float* __restrict__ a, float* __restrict__ da, int n1,
    const float* __restrict__ b, float* __restrict__ db, int n2,
    const float* __restrict__ c, float* __restrict__ dc, int n3) {
    int i = blockIdx.x * blockDim.x + threadIdx.x;
    int total = n1 + n2 + n3;
    for (; i < total; i += gridDim.x * blockDim.x) {
        const float* s;
        float* d;
        int j = i;
        if (j < n1) { s = a; d = da; }
        else if (j < n1 + n2) { j -= n1; s = b; d = db; }
        else { j -= n1 + n2; s = c; d = dc; }
        float4 v = ((const float4*)s)[j];
        uint4 u = make_uint4(f2tf(v.x), f2tf(v.y), f2tf(v.z), f2tf(v.w));
        ((uint4*)d)[j] = u;
    }
}

// ---------------- tf32 GEMM (known-good R2 config): C = A * B^T ------------
// 128x128 tile, 8 warps (2m x 4n), warp tile 64x32, k-step 16,
// 3-stage cp.async pipeline, smem row stride 20 u32 (conflict-free frags).
#define GS 20
#define GSTG (128 * GS)          // per-tensor per-stage u32
#define GEMM_SMEM_BYTES (3 * 2 * GSTG * 4)

__global__ __launch_bounds__(256, 2) void gemm_tf32(const float* __restrict__ A,
                                                    const float* __restrict__ B,
                                                    float* __restrict__ C,
                                                    int M, int N, int K) {
    extern __shared__ __align__(16) uint32_t gsm[];
    const int tid = threadIdx.x;
    const int m0 = blockIdx.y * 128;
    const int n0 = blockIdx.x * 128;
    const int warp = tid >> 5;
    const int lane = tid & 31;
    const int gid = lane >> 2;
    const int tig = lane & 3;
    const int wm = (warp & 1) * 64;
    const int wn = (warp >> 1) * 32;

    auto issue = [&](int k0, int s) {
        uint32_t* As = gsm + s * 2 * GSTG;
        uint32_t* Bs = As + GSTG;
#pragma unroll
        for (int i = 0; i < 4; i++) {
            int id = tid + 256 * i;       // 0..1023
            int rid = id & 511;
            int row = rid >> 2, c4 = (rid & 3) << 2;
            const float* src = (id < 512)
                ? A + (size_t)(m0 + row) * K + k0 + c4
                : B + (size_t)(n0 + row) * K + k0 + c4;
            uint32_t* dst = ((id < 512) ? As : Bs) + row * GS + c4;
            cp16(dst, src);
        }
        asm volatile("cp.async.commit_group;");
    };

    float acc[4][4][4];
#pragma unroll
    for (int mi = 0; mi < 4; mi++)
#pragma unroll
        for (int ni = 0; ni < 4; ni++)
#pragma unroll
            for (int f = 0; f < 4; f++) acc[mi][ni][f] = 0.f;

    const int nIter = K / 16;
    issue(0, 0);
    issue(16, 1);

    for (int it = 0; it < nIter; it++) {
        asm volatile("cp.async.wait_group 1;");
        __syncthreads();
        if (it + 2 < nIter) issue((it + 2) * 16, (it + 2) % 3);
        else asm volatile("cp.async.commit_group;");

        const uint32_t* As = gsm + (it % 3) * 2 * GSTG;
        const uint32_t* Bs = As + GSTG;
#pragma unroll
        for (int ks = 0; ks < 16; ks += 8) {
            uint32_t af[4][4], bf[4][2];
#pragma unroll
            for (int mi = 0; mi < 4; mi++) {
                int r = (wm + 16 * mi + gid) * GS + ks + tig;
                af[mi][0] = As[r];
                af[mi][1] = As[r + 8 * GS];
                af[mi][2] = As[r + 4];
                af[mi][3] = As[r + 8 * GS + 4];
            }
#pragma unroll
            for (int ni = 0; ni < 4; ni++) {
                int r = (wn + 8 * ni + gid) * GS + ks + tig;
                bf[ni][0] = Bs[r];
                bf[ni][1] = Bs[r + 4];
            }
#pragma unroll
            for (int mi = 0; mi < 4; mi++)
#pragma unroll
                for (int ni = 0; ni < 4; ni++) mma_tf32(acc[mi][ni], af[mi], bf[ni]);
        }
    }

#pragma unroll
    for (int mi = 0; mi < 4; mi++) {
        int r0 = m0 + wm + 16 * mi + gid;
#pragma unroll
        for (int ni = 0; ni < 4; ni++) {
            int c = n0 + wn + 8 * ni + 2 * tig;
            *(float2*)(C + (size_t)r0 * N + c) = make_float2(acc[mi][ni][0], acc[mi][ni][1]);
            *(float2*)(C + (size_t)(r0 + 8) * N + c) = make_float2(acc[mi][ni][2], acc[mi][ni][3]);
        }
    }
}

// ---------------- prep: RMSNorm + RoPE + gain, outputs tf32-rounded --------
__global__ __launch_bounds__(256) void prep_kernel(const float* __restrict__ qkv,
                                                   const float* __restrict__ gain) {
    const int warp = blockIdx.x * 8 + (threadIdx.x >> 5);
    const int lane = threadIdx.x & 31;
    const int NQ = TSEQ * NH;
    const int NK = TSEQ * NKV;
    if (warp >= NQ + 2 * NK) return;

    if (warp < NQ + NK) {
        int t, off;
        float g;
        float* dst;
        if (warp < NQ) {
            t = warp / NH;
            int h = warp % NH;
            off = h * HDIM;
            g = gain[h];
            dst = g_q + ((size_t)h * TSEQ + t) * HDIM;
        } else {
            int w = warp - NQ;
            t = w / NKV;
            int kv = w % NKV;
            off = KVOFF + kv * HDIM;
            g = 1.0f;
            dst = g_k + ((size_t)kv * TSEQ + t) * HDIM;
        }
        const float* src = qkv + (size_t)t * QKVD + off;
        float x1 = src[lane], x2 = src[lane + 32];
        float ss = x1 * x1 + x2 * x2;
        ss += __shfl_xor_sync(0xffffffffu, ss, 16);
        ss += __shfl_xor_sync(0xffffffffu, ss, 8);
        ss += __shfl_xor_sync(0xffffffffu, ss, 4);
        ss += __shfl_xor_sync(0xffffffffu, ss, 2);
        ss += __shfl_xor_sync(0xffffffffu, ss, 1);
        float r = rsqrtf(ss * (1.0f / 64.0f) + 1.1920929e-07f);
        x1 *= r; x2 *= r;
        float fr = (float)t * g_invf[lane];
        float s, c;
        sincosf(fr, &s, &c);
        dst[lane]      = __uint_as_float(f2tf((x1 * c + x2 * s) * g));
        dst[lane + 32] = __uint_as_float(f2tf((x2 * c - x1 * s) * g));
    } else {
        int w = warp - NQ - NK;
        int t = w / NKV, kv = w % NKV;
        const float* src = qkv + (size_t)t * QKVD + VOFF + kv * HDIM;
        float* dst = g_v + ((size_t)kv * TSEQ + t) * HDIM;
        dst[lane] = __uint_as_float(f2tf(src[lane]));
        dst[lane + 32] = __uint_as_float(f2tf(src[lane + 32]));
    }
}

// ---------------- flash attention: 128-row Q tile, 8 warps -----------------
// Q fragments in registers; K/V double-buffered cp.async; P straight from
// registers into the PV mma (permuted-V trick). NO online max: with
// rmsnormed q,k (norm 8 each, gain 1) s*cs <= 11.54, so P = 2^(s*cs - 8)
// never overflows; the 2^-8 cancels in P/l. l accumulated per-lane, reduced
// once in the epilogue.
#define KSR 68
#define VSR 68
#define ATTN_SMEM_U32 (2 * 64 * KSR + 2 * 64 * VSR)
#define ATTN_SMEM_BYTES (ATTN_SMEM_U32 * 4)

__global__ __launch_bounds__(256, 2) void attn_kernel() {
    extern __shared__ __align__(16) uint32_t smu[];
    uint32_t* Kb = smu;                    // [2][64][68]
    uint32_t* Vb = smu + 2 * 64 * KSR;     // [2][64][68]

    const int tid = threadIdx.x;
    const int h = blockIdx.y;
    const int qb = (int)gridDim.x - 1 - (int)blockIdx.x;  // heavy CTAs first
    const int kvh = h >> 2;
    const int lane = tid & 31;
    const int warp = tid >> 5;
    const int gid = lane >> 2;
    const int tig = lane & 3;
    const int q0w = warp * 16;
    const int kbmax = 2 * qb + 1;

    const float* kbase = g_k + ((size_t)kvh * TSEQ) * HDIM;
    const float* vbase = g_v + ((size_t)kvh * TSEQ) * HDIM;

    auto issueKV = [&](int kb) {
        const float* kp = kbase + (size_t)kb * 64 * HDIM;
        const float* vp = vbase + (size_t)kb * 64 * HDIM;
        uint32_t* Kd = Kb + (kb & 1) * 64 * KSR;
        uint32_t* Vd = Vb + (kb & 1) * 64 * VSR;
#pragma unroll
        for (int i = 0; i < 4; i++) {
            int slot = tid + 256 * i;       // 0..1023 = 64 rows x 16 chunks
            int row = slot >> 4, c4 = (slot & 15) << 2;
            cp16(Kd + row * KSR + c4, kp + row * HDIM + c4);
            cp16(Vd + row * VSR + c4, vp + row * HDIM + c4);
        }
        asm volatile("cp.async.commit_group;");
    };

    // ---- stage Q tile through the K/V smem area, then frags -> registers ----
    {
        const float* qp = g_q + ((size_t)h * TSEQ + (size_t)qb * 128) * HDIM;
#pragma unroll
        for (int i = 0; i < 8; i++) {
            int slot = tid + 256 * i;       // 0..2047 = 128 rows x 16 chunks
            int row = slot >> 4, c4 = (slot & 15) << 2;
            *(float4*)&smu[row * KSR + c4] = *(const float4*)(qp + row * HDIM + c4);
        }
    }
    __syncthreads();
    uint32_t Qf[8][4];
#pragma unroll
    for (int ks = 0; ks < 8; ks++) {
        int r = (q0w + gid) * KSR + 8 * ks + tig;
        Qf[ks][0] = smu[r];
        Qf[ks][1] = smu[r + 8 * KSR];
        Qf[ks][2] = smu[r + 4];
        Qf[ks][3] = smu[r + 8 * KSR + 4];
    }
    __syncthreads();   // Q frags read; smem now free for K/V

    issueKV(0);

    float of[8][4];
    float s0 = 0.f, s1 = 0.f;
#pragma unroll
    for (int ni = 0; ni < 8; ni++)
#pragma unroll
        for (int f = 0; f < 4; f++) of[ni][f] = 0.f;

    const float cs = 0.18033688011112042f;  // (1/8) * log2(e)
    const int r0g = qb * 128 + q0w + gid;
    const int r1g = r0g + 8;

    for (int kb = 0; kb <= kbmax; kb++) {
        asm volatile("cp.async.wait_group 0;");
        __syncthreads();   // KV[cur] visible to all; prev iter fully done
        if (kb < kbmax) issueKV(kb + 1);

        const uint32_t* Kc = Kb + (kb & 1) * 64 * KSR;
        const uint32_t* Vc = Vb + (kb & 1) * 64 * VSR;

        // ---- S = Q K^T ----
        float sf[8][4];
#pragma unroll
        for (int ni = 0; ni < 8; ni++)
#pragma unroll
            for (int f = 0; f < 4; f++) sf[ni][f] = 0.f;

#pragma unroll
        for (int ks = 0; ks < 8; ks++) {
#pragma unroll
            for (int ni = 0; ni < 8; ni++) {
                uint32_t b[2];
                int r = (8 * ni + gid) * KSR + 8 * ks + tig;
                b[0] = Kc[r];
                b[1] = Kc[r + 4];
                mma_tf32(sf[ni], Qf[ks], b);
            }
        }

        // ---- P = 2^(s*cs - 8) with causal mask; accumulate l per lane ----
        if (kb >= 2 * qb) {
#pragma unroll
            for (int ni = 0; ni < 8; ni++) {
                int c0 = kb * 64 + 8 * ni + 2 * tig, c1 = c0 + 1;
                sf[ni][0] = (c0 <= r0g) ? fmaf(sf[ni][0], cs, -8.f) : -INFINITY;
                sf[ni][1] = (c1 <= r0g) ? fmaf(sf[ni][1], cs, -8.f) : -INFINITY;
                sf[ni][2] = (c0 <= r1g) ? fmaf(sf[ni][2], cs, -8.f) : -INFINITY;
                sf[ni][3] = (c1 <= r1g) ? fmaf(sf[ni][3], cs, -8.f) : -INFINITY;
            }
        } else {
#pragma unroll
            for (int ni = 0; ni < 8; ni++)
#pragma unroll
                for (int f = 0; f < 4; f++) sf[ni][f] = fmaf(sf[ni][f], cs, -8.f);
        }
#pragma unroll
        for (int ni = 0; ni < 8; ni++) {
            sf[ni][0] = ex2(sf[ni][0]);
            sf[ni][1] = ex2(sf[ni][1]);
            sf[ni][2] = ex2(sf[ni][2]);
            sf[ni][3] = ex2(sf[ni][3]);
            s0 += sf[ni][0] + sf[ni][1];
            s1 += sf[ni][2] + sf[ni][3];
        }

        // ---- O += P V  (P straight from registers; V rows permuted) ----
#pragma unroll
        for (int ks = 0; ks < 8; ks++) {
            uint32_t a[4];
            a[0] = f2tf(sf[ks][0]);   // (row gid,   k = 8ks+2tig)
            a[1] = f2tf(sf[ks][2]);   // (row gid+8, k = 8ks+2tig)
            a[2] = f2tf(sf[ks][1]);   // (row gid,   k = 8ks+2tig+1)
            a[3] = f2tf(sf[ks][3]);   // (row gid+8, k = 8ks+2tig+1)
            int rv0 = (8 * ks + 2 * tig) * VSR + gid;
            int rv1 = rv0 + VSR;
#pragma unroll
            for (int ni = 0; ni < 8; ni++) {
                uint32_t b[2];
                b[0] = Vc[rv0 + 8 * ni];
                b[1] = Vc[rv1 + 8 * ni];
                mma_tf32(of[ni], a, b);
            }
        }
    }

    // ---- epilogue: reduce l over quad lanes, normalize, store tf32 ----
    s0 += __shfl_xor_sync(0xffffffffu, s0, 1);
    s0 += __shfl_xor_sync(0xffffffffu, s0, 2);
    s1 += __shfl_xor_sync(0xffffffffu, s1, 1);
    s1 += __shfl_xor_sync(0xffffffffu, s1, 2);
    float inv0 = 1.0f / s0, inv1 = 1.0f / s1;
    float* ybase = g_y + (size_t)(qb * 128 + q0w + gid) * DIM + h * HDIM;
#pragma unroll
    for (int ni = 0; ni < 8; ni++) {
        int c = 8 * ni + 2 * tig;
        *(uint2*)(ybase + c) =
            make_uint2(f2tf(of[ni][0] * inv0), f2tf(of[ni][1] * inv0));
        *(uint2*)(ybase + 8 * DIM + c) =
            make_uint2(f2tf(of[ni][2] * inv1), f2tf(of[ni][3] * inv1));
    }
}

// ---------------- launch ---------------------------------------------------
extern "C" void kernel_launch(void* const* d_in, const int* in_sizes, int n_in,
                              void* d_out, int out_size) {
    const float* x      = (const float*)d_in[0];
    const float* w_qkv  = (const float*)d_in[1];
    const float* w_proj = (const float*)d_in[2];
    const float* q_gain = (const float*)d_in[3];
    float* out = (float*)d_out;

    float *qkv_p, *y_p, *xr_p, *wq_p, *wp_p;
    cudaGetSymbolAddress((void**)&qkv_p, g_qkv);
    cudaGetSymbolAddress((void**)&y_p, g_y);
    cudaGetSymbolAddress((void**)&xr_p, g_xr);
    cudaGetSymbolAddress((void**)&wq_p, g_wq);
    cudaGetSymbolAddress((void**)&wp_p, g_wp);

    // one-shot inv_freq (32 double pows total, not 2.6M)
    freq_kernel<<<1, 32>>>();

    // fused pre-round of x, w_qkv, w_proj (single launch)
    round3_kernel<<<1024, 256>>>(x, xr_p, TSEQ * DIM / 4,
                                 w_qkv, wq_p, QKVD * DIM / 4,
                                 w_proj, wp_p, DIM * DIM / 4);

    cudaFuncSetAttribute(gemm_tf32, cudaFuncAttributeMaxDynamicSharedMemorySize,
                         GEMM_SMEM_BYTES);
    gemm_tf32<<<dim3(QKVD / 128, TSEQ / 128), 256, GEMM_SMEM_BYTES>>>(
        xr_p, wq_p, qkv_p, TSEQ, QKVD, DIM);

    {
        int nwarps = TSEQ * (NH + 2 * NKV);
        prep_kernel<<<nwarps / 8, 256>>>(qkv_p, q_gain);
    }

    cudaFuncSetAttribute(attn_kernel, cudaFuncAttributeMaxDynamicSharedMemorySize,
                         ATTN_SMEM_BYTES);
    attn_kernel<<<dim3(TSEQ / 128, NH), 256, ATTN_SMEM_BYTES>>>();

    gemm_tf32<<<dim3(DIM / 128, TSEQ / 128), 256, GEMM_SMEM_BYTES>>>(
        y_p, wp_p, out, TSEQ, DIM, DIM);
}

// round 9
// speedup vs baseline: 3.4600x; 1.0623x over previous
#include <cuda_runtime.h>
#include <math.h>
#include <stdint.h>

#define TSEQ 4096
#define NH   16
#define NKV  4
#define HDIM 64
#define DIM  1024
#define QKVD 1536
#define KVOFF 1024
#define VOFF  1280

// ---------------- scratch (device globals; no cudaMalloc allowed) ----------
__device__ float g_qkv[TSEQ * QKVD];
__device__ float g_q[NH * TSEQ * HDIM];    // head-dim perm8-interleaved
__device__ float g_k[NKV * TSEQ * HDIM];   // head-dim perm8-interleaved
__device__ float g_v[NKV * TSEQ * HDIM];   // TRANSPOSED: [kv][d][t]
__device__ float g_y[TSEQ * DIM];          // DIM-axis perm16-interleaved
__device__ float g_xr[TSEQ * DIM];         // pre-rounded + perm16-interleaved
__device__ float g_wq[QKVD * DIM];
__device__ float g_wp[DIM * DIM];
__device__ float g_invf[32];

// ---------------- helpers ---------------------------------------------------
__device__ __forceinline__ uint32_t f2tf(float f) {
    uint32_t u;
    asm("cvt.rna.tf32.f32 %0, %1;" : "=r"(u) : "f"(f));
    return u;
}
__device__ __forceinline__ float ex2(float x) {
    float r;
    asm("ex2.approx.f32 %0, %1;" : "=f"(r) : "f"(x));
    return r;
}
__device__ __forceinline__ void mma_tf32(float c[4], const uint32_t a[4],
                                         const uint32_t b[2]) {
    asm volatile(
        "mma.sync.aligned.m16n8k8.row.col.f32.tf32.tf32.f32 "
        "{%0,%1,%2,%3}, {%4,%5,%6,%7}, {%8,%9}, {%0,%1,%2,%3};"
        : "+f"(c[0]), "+f"(c[1]), "+f"(c[2]), "+f"(c[3])
        : "r"(a[0]), "r"(a[1]), "r"(a[2]), "r"(a[3]), "r"(b[0]), "r"(b[1]));
}
__device__ __forceinline__ void cp16(void* smem_dst, const void* gsrc) {
    uint32_t s = (uint32_t)__cvta_generic_to_shared(smem_dst);
    asm volatile("cp.async.ca.shared.global [%0], [%1], 16;" :: "r"(s), "l"(gsrc));
}
// position of logical k within its 16-block: 4*(k%4) + k/4
__device__ __forceinline__ int perm16(int k) {
    return (k & ~15) | ((k & 3) << 2) | ((k >> 2) & 3);
}
// position of logical d within its 8-block: 2*(d%4) + (d/4)%2
__device__ __forceinline__ int perm8(int d) {
    return (d & ~7) | ((d & 3) << 1) | ((d >> 2) & 1);
}

// ---------------- one-shot inv_freq ----------------------------------------
__global__ void freq_kernel() {
    int l = threadIdx.x;
    g_invf[l] = (float)(1.0 / pow(10000.0, (double)l * (1.0 / 32.0)));
}

// ---------------- pre-round + perm16 interleave (K axis = 1024 all) --------
__global__ __launch_bounds__(256) void round3_kernel(
    const float* __restrict__ a, float* __restrict__ da, int n1,
    const float* __restrict__ b, float* __restrict__ db, int n2,
    const float* __restrict__ c, float* __restrict__ dc, int n3) {
    int i = blockIdx.x * blockDim.x + threadIdx.x;
    int total = n1 + n2 + n3;
    for (; i < total; i += gridDim.x * blockDim.x) {
        const float* s;
        float* d;
        int j = i;
        if (j < n1) { s = a; d = da; }
        else if (j < n1 + n2) { j -= n1; s = b; d = db; }
        else { j -= n1 + n2; s = c; d = dc; }
        float4 v = ((const float4*)s)[j];
        int e0 = j << 2;                 // logical element index
        int base = (e0 & ~15) | (j & 3); // +4*s gives permuted positions
        uint32_t* du = (uint32_t*)d;
        du[base]      = f2tf(v.x);
        du[base + 4]  = f2tf(v.y);
        du[base + 8]  = f2tf(v.z);
        du[base + 12] = f2tf(v.w);
    }
}

// ---------------- tf32 GEMM: C = A * B^T, perm16 inputs --------------------
// 128x128 tile, 8 warps (2m x 4n), k-step 16, 4-stage cp.async pipeline.
// smem stride 16 u32 (no pad; conflict-free for LDS.128 frag pattern).
#define GS 16
#define GSTG (128 * GS)
#define NSTAGE 4
#define GEMM_SMEM_BYTES (NSTAGE * 2 * GSTG * 4)

__global__ __launch_bounds__(256, 2) void gemm_tf32(const float* __restrict__ A,
                                                    const float* __restrict__ B,
                                                    float* __restrict__ C,
                                                    int M, int N, int K) {
    extern __shared__ __align__(16) uint32_t gsm[];
    const int tid = threadIdx.x;
    const int m0 = blockIdx.y * 128;
    const int n0 = blockIdx.x * 128;
    const int warp = tid >> 5;
    const int lane = tid & 31;
    const int gid = lane >> 2;
    const int tig = lane & 3;
    const int wm = (warp & 1) * 64;
    const int wn = (warp >> 1) * 32;

    auto issue = [&](int it) {
        int k0 = it * 16;
        uint32_t* As = gsm + (it & 3) * 2 * GSTG;
        uint32_t* Bs = As + GSTG;
#pragma unroll
        for (int i = 0; i < 4; i++) {
            int id = tid + 256 * i;       // 0..1023
            int rid = id & 511;
            int row = rid >> 2, c4 = (rid & 3) << 2;
            const float* src = (id < 512)
                ? A + (size_t)(m0 + row) * K + k0 + c4
                : B + (size_t)(n0 + row) * K + k0 + c4;
            uint32_t* dst = ((id < 512) ? As : Bs) + row * GS + c4;
            cp16(dst, src);
        }
        asm volatile("cp.async.commit_group;");
    };

    float acc[4][4][4];
#pragma unroll
    for (int mi = 0; mi < 4; mi++)
#pragma unroll
        for (int ni = 0; ni < 4; ni++)
#pragma unroll
            for (int f = 0; f < 4; f++) acc[mi][ni][f] = 0.f;

    const int nIter = K / 16;
    issue(0); issue(1); issue(2);

    for (int it = 0; it < nIter; it++) {
        asm volatile("cp.async.wait_group 2;");
        __syncthreads();
        if (it + 3 < nIter) issue(it + 3);
        else asm volatile("cp.async.commit_group;");

        const uint32_t* As = gsm + (it & 3) * 2 * GSTG;
        const uint32_t* Bs = As + GSTG;

        uint4 alo[4], ahi[4], bv[4];
#pragma unroll
        for (int mi = 0; mi < 4; mi++) {
            alo[mi] = *(const uint4*)&As[(wm + 16 * mi + gid) * GS + 4 * tig];
            ahi[mi] = *(const uint4*)&As[(wm + 16 * mi + gid + 8) * GS + 4 * tig];
        }
#pragma unroll
        for (int ni = 0; ni < 4; ni++)
            bv[ni] = *(const uint4*)&Bs[(wn + 8 * ni + gid) * GS + 4 * tig];

#pragma unroll
        for (int mi = 0; mi < 4; mi++) {
            uint32_t a0[4] = {alo[mi].x, ahi[mi].x, alo[mi].y, ahi[mi].y};
            uint32_t a1[4] = {alo[mi].z, ahi[mi].z, alo[mi].w, ahi[mi].w};
#pragma unroll
            for (int ni = 0; ni < 4; ni++) {
                uint32_t b0[2] = {bv[ni].x, bv[ni].y};
                uint32_t b1[2] = {bv[ni].z, bv[ni].w};
                mma_tf32(acc[mi][ni], a0, b0);
                mma_tf32(acc[mi][ni], a1, b1);
            }
        }
    }

#pragma unroll
    for (int mi = 0; mi < 4; mi++) {
        int r0 = m0 + wm + 16 * mi + gid;
#pragma unroll
        for (int ni = 0; ni < 4; ni++) {
            int c = n0 + wn + 8 * ni + 2 * tig;
            *(float2*)(C + (size_t)r0 * N + c) = make_float2(acc[mi][ni][0], acc[mi][ni][1]);
            *(float2*)(C + (size_t)(r0 + 8) * N + c) = make_float2(acc[mi][ni][2], acc[mi][ni][3]);
        }
    }
}

// ---------------- prep: RMSNorm + RoPE + gain -> perm8 tf32 ---------------
__global__ __launch_bounds__(256) void prep_kernel(const float* __restrict__ qkv,
                                                   const float* __restrict__ gain) {
    const int warp = blockIdx.x * 8 + (threadIdx.x >> 5);
    const int lane = threadIdx.x & 31;
    const int NQ = TSEQ * NH;
    const int NK = TSEQ * NKV;
    if (warp >= NQ + NK) return;

    int t, off;
    float g;
    float* dst;
    if (warp < NQ) {
        t = warp / NH;
        int h = warp % NH;
        off = h * HDIM;
        g = gain[h];
        dst = g_q + ((size_t)h * TSEQ + t) * HDIM;
    } else {
        int w = warp - NQ;
        t = w / NKV;
        int kv = w % NKV;
        off = KVOFF + kv * HDIM;
        g = 1.0f;
        dst = g_k + ((size_t)kv * TSEQ + t) * HDIM;
    }
    const float* src = qkv + (size_t)t * QKVD + off;
    float x1 = src[lane], x2 = src[lane + 32];
    float ss = x1 * x1 + x2 * x2;
    ss += __shfl_xor_sync(0xffffffffu, ss, 16);
    ss += __shfl_xor_sync(0xffffffffu, ss, 8);
    ss += __shfl_xor_sync(0xffffffffu, ss, 4);
    ss += __shfl_xor_sync(0xffffffffu, ss, 2);
    ss += __shfl_xor_sync(0xffffffffu, ss, 1);
    float r = rsqrtf(ss * (1.0f / 64.0f) + 1.1920929e-07f);
    x1 *= r; x2 *= r;
    float fr = (float)t * g_invf[lane];
    float s, c;
    sincosf(fr, &s, &c);
    dst[perm8(lane)]      = __uint_as_float(f2tf((x1 * c + x2 * s) * g));
    dst[perm8(lane + 32)] = __uint_as_float(f2tf((x2 * c - x1 * s) * g));
}

// ---------------- V transpose: qkv v-slice -> g_v[kv][d][t] (tf32) ---------
__global__ __launch_bounds__(256) void vtrans_kernel(const float* __restrict__ qkv) {
    __shared__ float ts[32][33];
    const int tx = threadIdx.x & 31;
    const int ty = threadIdx.x >> 5;
    const int t0 = blockIdx.x * 32;
    const int kv = blockIdx.y >> 1;
    const int d0 = (blockIdx.y & 1) * 32;
#pragma unroll
    for (int i = 0; i < 4; i++) {
        int row = ty + 8 * i;
        ts[row][tx] = qkv[(size_t)(t0 + row) * QKVD + VOFF + kv * HDIM + d0 + tx];
    }
    __syncthreads();
    float* vb = g_v + ((size_t)kv * HDIM) * TSEQ;
#pragma unroll
    for (int i = 0; i < 4; i++) {
        int d = d0 + ty + 8 * i;
        vb[(size_t)d * TSEQ + t0 + tx] = __uint_as_float(f2tf(ts[tx][ty + 8 * i]));
    }
}

// ---------------- flash attention: 128-row Q tile, 8 warps -----------------
// All fragment loads are LDS.64: K/Q via perm8 head-dim, V via transpose.
// Stride 72 (== 8 mod 32) -> conflict-free. P stays in registers.
#define KSR 72
#define VSR 72
#define ATTN_SMEM_U32 (2 * 64 * KSR + 2 * 64 * VSR)
#define ATTN_SMEM_BYTES (ATTN_SMEM_U32 * 4)

__global__ __launch_bounds__(256, 2) void attn_kernel() {
    extern __shared__ __align__(16) uint32_t smu[];
    uint32_t* Kb = smu;                    // [2][64][72]
    uint32_t* Vb = smu + 2 * 64 * KSR;     // [2][64][72]  (rows = d, cols = seq)

    const int tid = threadIdx.x;
    const int h = blockIdx.y;
    const int qb = (int)gridDim.x - 1 - (int)blockIdx.x;  // heavy CTAs first
    const int kvh = h >> 2;
    const int lane = tid & 31;
    const int warp = tid >> 5;
    const int gid = lane >> 2;
    const int tig = lane & 3;
    const int q0w = warp * 16;
    const int kbmax = 2 * qb + 1;

    const float* kbase = g_k + ((size_t)kvh * TSEQ) * HDIM;
    const float* vtbase = g_v + ((size_t)kvh * HDIM) * TSEQ;

    auto issueKV = [&](int kb) {
        const float* kp = kbase + (size_t)kb * 64 * HDIM;
        uint32_t* Kd = Kb + (kb & 1) * 64 * KSR;
        uint32_t* Vd = Vb + (kb & 1) * 64 * VSR;
#pragma unroll
        for (int i = 0; i < 4; i++) {
            int slot = tid + 256 * i;       // 0..1023 = 64 rows x 16 chunks
            int row = slot >> 4, c4 = (slot & 15) << 2;
            cp16(Kd + row * KSR + c4, kp + row * HDIM + c4);
            cp16(Vd + row * VSR + c4, vtbase + (size_t)row * TSEQ + kb * 64 + c4);
        }
        asm volatile("cp.async.commit_group;");
    };

    // ---- stage Q tile (perm8 layout, verbatim copy), frags -> registers ----
    {
        const float* qp = g_q + ((size_t)h * TSEQ + (size_t)qb * 128) * HDIM;
#pragma unroll
        for (int i = 0; i < 8; i++) {
            int slot = tid + 256 * i;       // 0..2047 = 128 rows x 16 chunks
            int row = slot >> 4, c4 = (slot & 15) << 2;
            *(float4*)&smu[row * KSR + c4] = *(const float4*)(qp + row * HDIM + c4);
        }
    }
    __syncthreads();
    uint32_t Qf[8][4];
#pragma unroll
    for (int ks = 0; ks < 8; ks++) {
        uint2 lo = *(const uint2*)&smu[(q0w + gid) * KSR + 8 * ks + 2 * tig];
        uint2 hi = *(const uint2*)&smu[(q0w + gid + 8) * KSR + 8 * ks + 2 * tig];
        Qf[ks][0] = lo.x; Qf[ks][1] = hi.x; Qf[ks][2] = lo.y; Qf[ks][3] = hi.y;
    }
    __syncthreads();   // Q frags read; smem now free for K/V

    issueKV(0);

    float of[8][4];
    float s0 = 0.f, s1 = 0.f;
#pragma unroll
    for (int ni = 0; ni < 8; ni++)
#pragma unroll
        for (int f = 0; f < 4; f++) of[ni][f] = 0.f;

    const float cs = 0.18033688011112042f;  // (1/8) * log2(e)
    const int r0g = qb * 128 + q0w + gid;
    const int r1g = r0g + 8;

    for (int kb = 0; kb <= kbmax; kb++) {
        asm volatile("cp.async.wait_group 0;");
        __syncthreads();
        if (kb < kbmax) issueKV(kb + 1);

        const uint32_t* Kc = Kb + (kb & 1) * 64 * KSR;
        const uint32_t* Vc = Vb + (kb & 1) * 64 * VSR;

        // ---- S = Q K^T ----
        float sf[8][4];
#pragma unroll
        for (int ni = 0; ni < 8; ni++)
#pragma unroll
            for (int f = 0; f < 4; f++) sf[ni][f] = 0.f;

#pragma unroll
        for (int ks = 0; ks < 8; ks++) {
#pragma unroll
            for (int ni = 0; ni < 8; ni++) {
                uint2 kb2 = *(const uint2*)&Kc[(8 * ni + gid) * KSR + 8 * ks + 2 * tig];
                uint32_t b[2] = {kb2.x, kb2.y};
                mma_tf32(sf[ni], Qf[ks], b);
            }
        }

        // ---- P = 2^(s*cs - 8) with causal mask; accumulate l per lane ----
        if (kb >= 2 * qb) {
#pragma unroll
            for (int ni = 0; ni < 8; ni++) {
                int c0 = kb * 64 + 8 * ni + 2 * tig, c1 = c0 + 1;
                sf[ni][0] = (c0 <= r0g) ? fmaf(sf[ni][0], cs, -8.f) : -INFINITY;
                sf[ni][1] = (c1 <= r0g) ? fmaf(sf[ni][1], cs, -8.f) : -INFINITY;
                sf[ni][2] = (c0 <= r1g) ? fmaf(sf[ni][2], cs, -8.f) : -INFINITY;
                sf[ni][3] = (c1 <= r1g) ? fmaf(sf[ni][3], cs, -8.f) : -INFINITY;
            }
        } else {
#pragma unroll
            for (int ni = 0; ni < 8; ni++)
#pragma unroll
                for (int f = 0; f < 4; f++) sf[ni][f] = fmaf(sf[ni][f], cs, -8.f);
        }
#pragma unroll
        for (int ni = 0; ni < 8; ni++) {
            sf[ni][0] = ex2(sf[ni][0]);
            sf[ni][1] = ex2(sf[ni][1]);
            sf[ni][2] = ex2(sf[ni][2]);
            sf[ni][3] = ex2(sf[ni][3]);
            s0 += sf[ni][0] + sf[ni][1];
            s1 += sf[ni][2] + sf[ni][3];
        }

        // ---- O += P V  (P from registers; V transposed, LDS.64 b-frags) ----
#pragma unroll
        for (int ks = 0; ks < 8; ks++) {
            uint32_t a[4];
            a[0] = f2tf(sf[ks][0]);   // (row gid,   seq 8ks+2tig)
            a[1] = f2tf(sf[ks][2]);   // (row gid+8, seq 8ks+2tig)
            a[2] = f2tf(sf[ks][1]);   // (row gid,   seq 8ks+2tig+1)
            a[3] = f2tf(sf[ks][3]);   // (row gid+8, seq 8ks+2tig+1)
#pragma unroll
            for (int ni = 0; ni < 8; ni++) {
                uint2 vb2 = *(const uint2*)&Vc[(8 * ni + gid) * VSR + 8 * ks + 2 * tig];
                uint32_t b[2] = {vb2.x, vb2.y};
                mma_tf32(of[ni], a, b);
            }
        }
    }

    // ---- epilogue: reduce l, normalize, store y perm16 tf32 ----
    s0 += __shfl_xor_sync(0xffffffffu, s0, 1);
    s0 += __shfl_xor_sync(0xffffffffu, s0, 2);
    s1 += __shfl_xor_sync(0xffffffffu, s1, 1);
    s1 += __shfl_xor_sync(0xffffffffu, s1, 2);
    float inv0 = 1.0f / s0, inv1 = 1.0f / s1;
    float* ybase = g_y + (size_t)(qb * 128 + q0w + gid) * DIM + h * HDIM;
#pragma unroll
    for (int ni = 0; ni < 8; ni++) {
        int c0 = 8 * ni + 2 * tig, c1 = c0 + 1;
        int p0 = perm16(c0), p1 = perm16(c1);
        ybase[p0] = __uint_as_float(f2tf(of[ni][0] * inv0));
        ybase[p1] = __uint_as_float(f2tf(of[ni][1] * inv0));
        ybase[8 * DIM + p0] = __uint_as_float(f2tf(of[ni][2] * inv1));
        ybase[8 * DIM + p1] = __uint_as_float(f2tf(of[ni][3] * inv1));
    }
}

// ---------------- launch ---------------------------------------------------
extern "C" void kernel_launch(void* const* d_in, const int* in_sizes, int n_in,
                              void* d_out, int out_size) {
    const float* x      = (const float*)d_in[0];
    const float* w_qkv  = (const float*)d_in[1];
    const float* w_proj = (const float*)d_in[2];
    const float* q_gain = (const float*)d_in[3];
    float* out = (float*)d_out;

    float *qkv_p, *y_p, *xr_p, *wq_p, *wp_p;
    cudaGetSymbolAddress((void**)&qkv_p, g_qkv);
    cudaGetSymbolAddress((void**)&y_p, g_y);
    cudaGetSymbolAddress((void**)&xr_p, g_xr);
    cudaGetSymbolAddress((void**)&wq_p, g_wq);
    cudaGetSymbolAddress((void**)&wp_p, g_wp);

    freq_kernel<<<1, 32>>>();

    round3_kernel<<<1024, 256>>>(x, xr_p, TSEQ * DIM / 4,
                                 w_qkv, wq_p, QKVD * DIM / 4,
                                 w_proj, wp_p, DIM * DIM / 4);

    cudaFuncSetAttribute(gemm_tf32, cudaFuncAttributeMaxDynamicSharedMemorySize,
                         GEMM_SMEM_BYTES);
    gemm_tf32<<<dim3(QKVD / 128, TSEQ / 128), 256, GEMM_SMEM_BYTES>>>(
        xr_p, wq_p, qkv_p, TSEQ, QKVD, DIM);

    {
        int nwarps = TSEQ * (NH + NKV);
        prep_kernel<<<nwarps / 8, 256>>>(qkv_p, q_gain);
    }
    vtrans_kernel<<<dim3(TSEQ / 32, NKV * 2), 256>>>(qkv_p);

    cudaFuncSetAttribute(attn_kernel, cudaFuncAttributeMaxDynamicSharedMemorySize,
                         ATTN_SMEM_BYTES);
    attn_kernel<<<dim3(TSEQ / 128, NH), 256, ATTN_SMEM_BYTES>>>();

    gemm_tf32<<<dim3(DIM / 128, TSEQ / 128), 256, GEMM_SMEM_BYTES>>>(
        y_p, wp_p, out, TSEQ, DIM, DIM);
}

// round 12
// speedup vs baseline: 3.4946x; 1.0100x over previous
#include <cuda_runtime.h>
#include <math.h>
#include <stdint.h>

#define TSEQ 4096
#define NH   16
#define NKV  4
#define HDIM 64
#define DIM  1024
#define QKVD 1536
#define KVOFF 1024
#define VOFF  1280

// ---------------- scratch (device globals; no cudaMalloc allowed) ----------
__device__ float g_qkv[TSEQ * QKVD];
__device__ float g_q[NH * TSEQ * HDIM];    // head-dim perm8-interleaved
__device__ float g_k[NKV * TSEQ * HDIM];   // head-dim perm8-interleaved
__device__ float g_v[NKV * TSEQ * HDIM];   // TRANSPOSED: [kv][d][t]
__device__ float g_y[TSEQ * DIM];          // DIM-axis perm16-interleaved
__device__ float g_xr[TSEQ * DIM];         // pre-rounded + perm16-interleaved
__device__ float g_wq[QKVD * DIM];
__device__ float g_wp[DIM * DIM];
__device__ float g_invf[32];

// ---------------- helpers ---------------------------------------------------
__device__ __forceinline__ uint32_t f2tf(float f) {
    uint32_t u;
    asm("cvt.rna.tf32.f32 %0, %1;" : "=r"(u) : "f"(f));
    return u;
}
__device__ __forceinline__ float ex2(float x) {
    float r;
    asm("ex2.approx.f32 %0, %1;" : "=f"(r) : "f"(x));
    return r;
}
__device__ __forceinline__ void mma_tf32(float c[4], const uint32_t a[4],
                                         const uint32_t b[2]) {
    asm volatile(
        "mma.sync.aligned.m16n8k8.row.col.f32.tf32.tf32.f32 "
        "{%0,%1,%2,%3}, {%4,%5,%6,%7}, {%8,%9}, {%0,%1,%2,%3};"
        : "+f"(c[0]), "+f"(c[1]), "+f"(c[2]), "+f"(c[3])
        : "r"(a[0]), "r"(a[1]), "r"(a[2]), "r"(a[3]), "r"(b[0]), "r"(b[1]));
}
__device__ __forceinline__ void cp16(void* smem_dst, const void* gsrc) {
    uint32_t s = (uint32_t)__cvta_generic_to_shared(smem_dst);
    asm volatile("cp.async.ca.shared.global [%0], [%1], 16;" :: "r"(s), "l"(gsrc));
}
// position of logical k within its 16-block: 4*(k%4) + k/4
__device__ __forceinline__ int perm16(int k) {
    return (k & ~15) | ((k & 3) << 2) | ((k >> 2) & 3);
}
// position of logical d within its 8-block: 2*(d%4) + (d/4)%2
__device__ __forceinline__ int perm8(int d) {
    return (d & ~7) | ((d & 3) << 1) | ((d >> 2) & 1);
}

// ---------------- one-shot inv_freq ----------------------------------------
__global__ void freq_kernel() {
    int l = threadIdx.x;
    g_invf[l] = (float)(1.0 / pow(10000.0, (double)l * (1.0 / 32.0)));
}

// ---------------- pre-round + perm16 interleave (K axis = 1024 all) --------
__global__ __launch_bounds__(256) void round3_kernel(
    const float* __restrict__ a, float* __restrict__ da, int n1,
    const float* __restrict__ b, float* __restrict__ db, int n2,
    const float* __restrict__ c, float* __restrict__ dc, int n3) {
    int i = blockIdx.x * blockDim.x + threadIdx.x;
    int total = n1 + n2 + n3;
    for (; i < total; i += gridDim.x * blockDim.x) {
        const float* s;
        float* d;
        int j = i;
        if (j < n1) { s = a; d = da; }
        else if (j < n1 + n2) { j -= n1; s = b; d = db; }
        else { j -= n1 + n2; s = c; d = dc; }
        float4 v = ((const float4*)s)[j];
        int e0 = j << 2;                 // logical element index
        int base = (e0 & ~15) | (j & 3); // +4*s gives permuted positions
        uint32_t* du = (uint32_t*)d;
        du[base]      = f2tf(v.x);
        du[base + 4]  = f2tf(v.y);
        du[base + 8]  = f2tf(v.z);
        du[base + 12] = f2tf(v.w);
    }
}

// ---------------- tf32 GEMM: C = A * B^T, perm16 inputs --------------------
// 128x128 tile, 8 warps (2m x 4n), k-step 16, 4-stage cp.async pipeline.
// smem stride 16 u32 (no pad; conflict-free for LDS.128 frag pattern).
#define GS 16
#define GSTG (128 * GS)
#define NSTAGE 4
#define GEMM_SMEM_BYTES (NSTAGE * 2 * GSTG * 4)

__global__ __launch_bounds__(256, 2) void gemm_tf32(const float* __restrict__ A,
                                                    const float* __restrict__ B,
                                                    float* __restrict__ C,
                                                    int M, int N, int K) {
    extern __shared__ __align__(16) uint32_t gsm[];
    const int tid = threadIdx.x;
    const int m0 = blockIdx.y * 128;
    const int n0 = blockIdx.x * 128;
    const int warp = tid >> 5;
    const int lane = tid & 31;
    const int gid = lane >> 2;
    const int tig = lane & 3;
    const int wm = (warp & 1) * 64;
    const int wn = (warp >> 1) * 32;

    auto issue = [&](int it) {
        int k0 = it * 16;
        uint32_t* As = gsm + (it & 3) * 2 * GSTG;
        uint32_t* Bs = As + GSTG;
#pragma unroll
        for (int i = 0; i < 4; i++) {
            int id = tid + 256 * i;       // 0..1023
            int rid = id & 511;
            int row = rid >> 2, c4 = (rid & 3) << 2;
            const float* src = (id < 512)
                ? A + (size_t)(m0 + row) * K + k0 + c4
                : B + (size_t)(n0 + row) * K + k0 + c4;
            uint32_t* dst = ((id < 512) ? As : Bs) + row * GS + c4;
            cp16(dst, src);
        }
        asm volatile("cp.async.commit_group;");
    };

    float acc[4][4][4];
#pragma unroll
    for (int mi = 0; mi < 4; mi++)
#pragma unroll
        for (int ni = 0; ni < 4; ni++)
#pragma unroll
            for (int f = 0; f < 4; f++) acc[mi][ni][f] = 0.f;

    const int nIter = K / 16;
    issue(0); issue(1); issue(2);

    for (int it = 0; it < nIter; it++) {
        asm volatile("cp.async.wait_group 2;");
        __syncthreads();
        if (it + 3 < nIter) issue(it + 3);
        else asm volatile("cp.async.commit_group;");

        const uint32_t* As = gsm + (it & 3) * 2 * GSTG;
        const uint32_t* Bs = As + GSTG;

        uint4 alo[4], ahi[4], bv[4];
#pragma unroll
        for (int mi = 0; mi < 4; mi++) {
            alo[mi] = *(const uint4*)&As[(wm + 16 * mi + gid) * GS + 4 * tig];
            ahi[mi] = *(const uint4*)&As[(wm + 16 * mi + gid + 8) * GS + 4 * tig];
        }
#pragma unroll
        for (int ni = 0; ni < 4; ni++)
            bv[ni] = *(const uint4*)&Bs[(wn + 8 * ni + gid) * GS + 4 * tig];

#pragma unroll
        for (int mi = 0; mi < 4; mi++) {
            uint32_t a0[4] = {alo[mi].x, ahi[mi].x, alo[mi].y, ahi[mi].y};
            uint32_t a1[4] = {alo[mi].z, ahi[mi].z, alo[mi].w, ahi[mi].w};
#pragma unroll
            for (int ni = 0; ni < 4; ni++) {
                uint32_t b0[2] = {bv[ni].x, bv[ni].y};
                uint32_t b1[2] = {bv[ni].z, bv[ni].w};
                mma_tf32(acc[mi][ni], a0, b0);
                mma_tf32(acc[mi][ni], a1, b1);
            }
        }
    }

#pragma unroll
    for (int mi = 0; mi < 4; mi++) {
        int r0 = m0 + wm + 16 * mi + gid;
#pragma unroll
        for (int ni = 0; ni < 4; ni++) {
            int c = n0 + wn + 8 * ni + 2 * tig;
            *(float2*)(C + (size_t)r0 * N + c) = make_float2(acc[mi][ni][0], acc[mi][ni][1]);
            *(float2*)(C + (size_t)(r0 + 8) * N + c) = make_float2(acc[mi][ni][2], acc[mi][ni][3]);
        }
    }
}

// ---------------- prep: RMSNorm + RoPE + gain -> perm8 tf32 ---------------
__global__ __launch_bounds__(256) void prep_kernel(const float* __restrict__ qkv,
                                                   const float* __restrict__ gain) {
    const int warp = blockIdx.x * 8 + (threadIdx.x >> 5);
    const int lane = threadIdx.x & 31;
    const int NQ = TSEQ * NH;
    const int NK = TSEQ * NKV;
    if (warp >= NQ + NK) return;

    int t, off;
    float g;
    float* dst;
    if (warp < NQ) {
        t = warp / NH;
        int h = warp % NH;
        off = h * HDIM;
        g = gain[h];
        dst = g_q + ((size_t)h * TSEQ + t) * HDIM;
    } else {
        int w = warp - NQ;
        t = w / NKV;
        int kv = w % NKV;
        off = KVOFF + kv * HDIM;
        g = 1.0f;
        dst = g_k + ((size_t)kv * TSEQ + t) * HDIM;
    }
    const float* src = qkv + (size_t)t * QKVD + off;
    float x1 = src[lane], x2 = src[lane + 32];
    float ss = x1 * x1 + x2 * x2;
    ss += __shfl_xor_sync(0xffffffffu, ss, 16);
    ss += __shfl_xor_sync(0xffffffffu, ss, 8);
    ss += __shfl_xor_sync(0xffffffffu, ss, 4);
    ss += __shfl_xor_sync(0xffffffffu, ss, 2);
    ss += __shfl_xor_sync(0xffffffffu, ss, 1);
    float r = rsqrtf(ss * (1.0f / 64.0f) + 1.1920929e-07f);
    x1 *= r; x2 *= r;
    float fr = (float)t * g_invf[lane];
    float s, c;
    sincosf(fr, &s, &c);
    dst[perm8(lane)]      = __uint_as_float(f2tf((x1 * c + x2 * s) * g));
    dst[perm8(lane + 32)] = __uint_as_float(f2tf((x2 * c - x1 * s) * g));
}

// ---------------- V transpose: qkv v-slice -> g_v[kv][d][t] (tf32) ---------
__global__ __launch_bounds__(256) void vtrans_kernel(const float* __restrict__ qkv) {
    __shared__ float ts[32][33];
    const int tx = threadIdx.x & 31;
    const int ty = threadIdx.x >> 5;
    const int t0 = blockIdx.x * 32;
    const int kv = blockIdx.y >> 1;
    const int d0 = (blockIdx.y & 1) * 32;
#pragma unroll
    for (int i = 0; i < 4; i++) {
        int row = ty + 8 * i;
        ts[row][tx] = qkv[(size_t)(t0 + row) * QKVD + VOFF + kv * HDIM + d0 + tx];
    }
    __syncthreads();
    float* vb = g_v + ((size_t)kv * HDIM) * TSEQ;
#pragma unroll
    for (int i = 0; i < 4; i++) {
        int d = d0 + ty + 8 * i;
        vb[(size_t)d * TSEQ + t0 + tx] = __uint_as_float(f2tf(ts[tx][ty + 8 * i]));
    }
}

// ---------------- flash attention: 128-row Q tile, 8 warps -----------------
// FUSED tile body: per 8-col seq chunk, S-mma -> mask -> ex2 -> cvt -> PV-mma
// so tensor / MUFU / FMA / CVT work from neighboring chunks overlaps.
// Accumulation orders identical to the 3-phase version (bit-identical result).
#define KSR 72
#define VSR 72
#define ATTN_SMEM_U32 (2 * 64 * KSR + 2 * 64 * VSR)
#define ATTN_SMEM_BYTES (ATTN_SMEM_U32 * 4)

__global__ __launch_bounds__(256, 2) void attn_kernel() {
    extern __shared__ __align__(16) uint32_t smu[];
    uint32_t* Kb = smu;                    // [2][64][72]
    uint32_t* Vb = smu + 2 * 64 * KSR;     // [2][64][72]  (rows = d, cols = seq)

    const int tid = threadIdx.x;
    const int h = blockIdx.y;
    const int qb = (int)gridDim.x - 1 - (int)blockIdx.x;  // heavy CTAs first
    const int kvh = h >> 2;
    const int lane = tid & 31;
    const int warp = tid >> 5;
    const int gid = lane >> 2;
    const int tig = lane & 3;
    const int q0w = warp * 16;
    const int kbmax = 2 * qb + 1;

    const float* kbase = g_k + ((size_t)kvh * TSEQ) * HDIM;
    const float* vtbase = g_v + ((size_t)kvh * HDIM) * TSEQ;

    auto issueKV = [&](int kb) {
        const float* kp = kbase + (size_t)kb * 64 * HDIM;
        uint32_t* Kd = Kb + (kb & 1) * 64 * KSR;
        uint32_t* Vd = Vb + (kb & 1) * 64 * VSR;
#pragma unroll
        for (int i = 0; i < 4; i++) {
            int slot = tid + 256 * i;       // 0..1023 = 64 rows x 16 chunks
            int row = slot >> 4, c4 = (slot & 15) << 2;
            cp16(Kd + row * KSR + c4, kp + row * HDIM + c4);
            cp16(Vd + row * VSR + c4, vtbase + (size_t)row * TSEQ + kb * 64 + c4);
        }
        asm volatile("cp.async.commit_group;");
    };

    // ---- stage Q tile (perm8 layout, verbatim copy), frags -> registers ----
    {
        const float* qp = g_q + ((size_t)h * TSEQ + (size_t)qb * 128) * HDIM;
#pragma unroll
        for (int i = 0; i < 8; i++) {
            int slot = tid + 256 * i;       // 0..2047 = 128 rows x 16 chunks
            int row = slot >> 4, c4 = (slot & 15) << 2;
            *(float4*)&smu[row * KSR + c4] = *(const float4*)(qp + row * HDIM + c4);
        }
    }
    __syncthreads();
    uint32_t Qf[8][4];
#pragma unroll
    for (int ks = 0; ks < 8; ks++) {
        uint2 lo = *(const uint2*)&smu[(q0w + gid) * KSR + 8 * ks + 2 * tig];
        uint2 hi = *(const uint2*)&smu[(q0w + gid + 8) * KSR + 8 * ks + 2 * tig];
        Qf[ks][0] = lo.x; Qf[ks][1] = hi.x; Qf[ks][2] = lo.y; Qf[ks][3] = hi.y;
    }
    __syncthreads();   // Q frags read; smem now free for K/V

    issueKV(0);

    float of[8][4];
    float s0 = 0.f, s1 = 0.f;
#pragma unroll
    for (int ni = 0; ni < 8; ni++)
#pragma unroll
        for (int f = 0; f < 4; f++) of[ni][f] = 0.f;

    const float cs = 0.18033688011112042f;  // (1/8) * log2(e)
    const int r0g = qb * 128 + q0w + gid;
    const int r1g = r0g + 8;

    for (int kb = 0; kb <= kbmax; kb++) {
        asm volatile("cp.async.wait_group 0;");
        __syncthreads();
        if (kb < kbmax) issueKV(kb + 1);

        const uint32_t* Kc = Kb + (kb & 1) * 64 * KSR;
        const uint32_t* Vc = Vb + (kb & 1) * 64 * VSR;
        const bool diag = (kb >= 2 * qb);

#pragma unroll
        for (int ni = 0; ni < 8; ni++) {
            // ---- S chunk = Q K^T (8 seq cols) ----
            float sf[4] = {0.f, 0.f, 0.f, 0.f};
            const uint32_t* kr = &Kc[(8 * ni + gid) * KSR + 2 * tig];
#pragma unroll
            for (int kd = 0; kd < 8; kd++) {
                uint2 kb2 = *(const uint2*)&kr[8 * kd];
                uint32_t b[2] = {kb2.x, kb2.y};
                mma_tf32(sf, Qf[kd], b);
            }

            // ---- mask / scale*log2e - 8 ----
            if (diag) {
                int c0 = kb * 64 + 8 * ni + 2 * tig, c1 = c0 + 1;
                sf[0] = (c0 <= r0g) ? fmaf(sf[0], cs, -8.f) : -INFINITY;
                sf[1] = (c1 <= r0g) ? fmaf(sf[1], cs, -8.f) : -INFINITY;
                sf[2] = (c0 <= r1g) ? fmaf(sf[2], cs, -8.f) : -INFINITY;
                sf[3] = (c1 <= r1g) ? fmaf(sf[3], cs, -8.f) : -INFINITY;
            } else {
                sf[0] = fmaf(sf[0], cs, -8.f);
                sf[1] = fmaf(sf[1], cs, -8.f);
                sf[2] = fmaf(sf[2], cs, -8.f);
                sf[3] = fmaf(sf[3], cs, -8.f);
            }

            // ---- P = 2^(.), accumulate l ----
            sf[0] = ex2(sf[0]);
            sf[1] = ex2(sf[1]);
            sf[2] = ex2(sf[2]);
            sf[3] = ex2(sf[3]);
            s0 += sf[0] + sf[1];
            s1 += sf[2] + sf[3];

            // ---- O += P V (P from registers; V transposed) ----
            uint32_t a[4];
            a[0] = f2tf(sf[0]);   // (row gid,   seq 8ni+2tig)
            a[1] = f2tf(sf[2]);   // (row gid+8, seq 8ni+2tig)
            a[2] = f2tf(sf[1]);   // (row gid,   seq 8ni+2tig+1)
            a[3] = f2tf(sf[3]);   // (row gid+8, seq 8ni+2tig+1)
            const uint32_t* vr = &Vc[gid * VSR + 8 * ni + 2 * tig];
#pragma unroll
            for (int d = 0; d < 8; d++) {
                uint2 vb2 = *(const uint2*)&vr[8 * d * VSR];
                uint32_t b[2] = {vb2.x, vb2.y};
                mma_tf32(of[d], a, b);
            }
        }
    }

    // ---- epilogue: reduce l, normalize, store y perm16 tf32 ----
    s0 += __shfl_xor_sync(0xffffffffu, s0, 1);
    s0 += __shfl_xor_sync(0xffffffffu, s0, 2);
    s1 += __shfl_xor_sync(0xffffffffu, s1, 1);
    s1 += __shfl_xor_sync(0xffffffffu, s1, 2);
    float inv0 = 1.0f / s0, inv1 = 1.0f / s1;
    float* ybase = g_y + (size_t)(qb * 128 + q0w + gid) * DIM + h * HDIM;
#pragma unroll
    for (int ni = 0; ni < 8; ni++) {
        int c0 = 8 * ni + 2 * tig, c1 = c0 + 1;
        int p0 = perm16(c0), p1 = perm16(c1);
        ybase[p0] = __uint_as_float(f2tf(of[ni][0] * inv0));
        ybase[p1] = __uint_as_float(f2tf(of[ni][1] * inv0));
        ybase[8 * DIM + p0] = __uint_as_float(f2tf(of[ni][2] * inv1));
        ybase[8 * DIM + p1] = __uint_as_float(f2tf(of[ni][3] * inv1));
    }
}

// ---------------- launch ---------------------------------------------------
extern "C" void kernel_launch(void* const* d_in, const int* in_sizes, int n_in,
                              void* d_out, int out_size) {
    const float* x      = (const float*)d_in[0];
    const float* w_qkv  = (const float*)d_in[1];
    const float* w_proj = (const float*)d_in[2];
    const float* q_gain = (const float*)d_in[3];
    float* out = (float*)d_out;

    float *qkv_p, *y_p, *xr_p, *wq_p, *wp_p;
    cudaGetSymbolAddress((void**)&qkv_p, g_qkv);
    cudaGetSymbolAddress((void**)&y_p, g_y);
    cudaGetSymbolAddress((void**)&xr_p, g_xr);
    cudaGetSymbolAddress((void**)&wq_p, g_wq);
    cudaGetSymbolAddress((void**)&wp_p, g_wp);

    freq_kernel<<<1, 32>>>();

    round3_kernel<<<1024, 256>>>(x, xr_p, TSEQ * DIM / 4,
                                 w_qkv, wq_p, QKVD * DIM / 4,
                                 w_proj, wp_p, DIM * DIM / 4);

    cudaFuncSetAttribute(gemm_tf32, cudaFuncAttributeMaxDynamicSharedMemorySize,
                         GEMM_SMEM_BYTES);
    gemm_tf32<<<dim3(QKVD / 128, TSEQ / 128), 256, GEMM_SMEM_BYTES>>>(
        xr_p, wq_p, qkv_p, TSEQ, QKVD, DIM);

    {
        int nwarps = TSEQ * (NH + NKV);
        prep_kernel<<<nwarps / 8, 256>>>(qkv_p, q_gain);
    }
    vtrans_kernel<<<dim3(TSEQ / 32, NKV * 2), 256>>>(qkv_p);

    cudaFuncSetAttribute(attn_kernel, cudaFuncAttributeMaxDynamicSharedMemorySize,
                         ATTN_SMEM_BYTES);
    attn_kernel<<<dim3(TSEQ / 128, NH), 256, ATTN_SMEM_BYTES>>>();

    gemm_tf32<<<dim3(DIM / 128, TSEQ / 128), 256, GEMM_SMEM_BYTES>>>(
        y_p, wp_p, out, TSEQ, DIM, DIM);
}

// round 13
// speedup vs baseline: 6.5214x; 1.8661x over previous
#include <cuda_runtime.h>
#include <cuda_fp16.h>
#include <math.h>
#include <stdint.h>

#define TSEQ 4096
#define NH   16
#define NKV  4
#define HDIM 64
#define DIM  1024
#define QKVD 1536
#define KVOFF 1024
#define VOFF  1280

// ---------------- scratch (device globals; no cudaMalloc allowed) ----------
// float-declared, but several are used as __half (half capacity needed).
__device__ float g_qkv[TSEQ * QKVD];       // f32 (gemm1 output, prep input)
__device__ float g_q[NH * TSEQ * HDIM];    // half, d-axis word-perm8
__device__ float g_k[NKV * TSEQ * HDIM];   // half, d-axis word-perm8
__device__ float g_v[NKV * TSEQ * HDIM];   // half, TRANSPOSED [kv][d][t], t word-perm8
__device__ float g_y[TSEQ * DIM];          // half, DIM-axis word-perm8
__device__ float g_xr[TSEQ * DIM];         // half, K-axis word-perm8
__device__ float g_wq[QKVD * DIM];         // half, K-axis word-perm8
__device__ float g_wp[DIM * DIM];          // half, K-axis word-perm8
__device__ float g_invf[32];

// ---------------- helpers ---------------------------------------------------
__device__ __forceinline__ float ex2(float x) {
    float r;
    asm("ex2.approx.f32 %0, %1;" : "=f"(r) : "f"(x));
    return r;
}
__device__ __forceinline__ uint32_t f2h2(float lo, float hi) {
    __half2 h = __floats2half2_rn(lo, hi);   // .x = lo half
    return *(uint32_t*)&h;
}
__device__ __forceinline__ void mma_f16(float c[4], const uint32_t a[4],
                                        const uint32_t b[2]) {
    asm volatile(
        "mma.sync.aligned.m16n8k16.row.col.f32.f16.f16.f32 "
        "{%0,%1,%2,%3}, {%4,%5,%6,%7}, {%8,%9}, {%0,%1,%2,%3};"
        : "+f"(c[0]), "+f"(c[1]), "+f"(c[2]), "+f"(c[3])
        : "r"(a[0]), "r"(a[1]), "r"(a[2]), "r"(a[3]), "r"(b[0]), "r"(b[1]));
}
__device__ __forceinline__ void cp16(void* smem_dst, const void* gsrc) {
    uint32_t s = (uint32_t)__cvta_generic_to_shared(smem_dst);
    asm volatile("cp.async.ca.shared.global [%0], [%1], 16;" :: "r"(s), "l"(gsrc));
}
// word-perm within each 8-word (16-half) block: word w -> 2*(w%4) + (w/4)%2
__device__ __forceinline__ int wp8(int w) {
    return (w & ~7) | ((w & 3) << 1) | ((w >> 2) & 1);
}

// ---------------- one-shot inv_freq ----------------------------------------
__global__ void freq_kernel() {
    int l = threadIdx.x;
    g_invf[l] = (float)(1.0 / pow(10000.0, (double)l * (1.0 / 32.0)));
}

// ---------------- pre-round: f32 -> f16, K-axis word-perm8 -----------------
__global__ __launch_bounds__(256) void round3h_kernel(
    const float* __restrict__ a, __half* __restrict__ da, int n1,
    const float* __restrict__ b, __half* __restrict__ db, int n2,
    const float* __restrict__ c, __half* __restrict__ dc, int n3) {
    int i = blockIdx.x * blockDim.x + threadIdx.x;
    int total = n1 + n2 + n3;
    for (; i < total; i += gridDim.x * blockDim.x) {
        const float* s;
        __half* d;
        int j = i;
        if (j < n1) { s = a; d = da; }
        else if (j < n1 + n2) { j -= n1; s = b; d = db; }
        else { j -= n1 + n2; s = c; d = dc; }
        float4 v = ((const float4*)s)[j];
        uint32_t* du = (uint32_t*)d;
        int w0 = j << 1;
        du[wp8(w0)]     = f2h2(v.x, v.y);
        du[wp8(w0 + 1)] = f2h2(v.z, v.w);
    }
}

// ---------------- fp16 GEMM: C[M,N] = A[M,K] * B[N,K]^T --------------------
// A,B half, K-axis word-perm8. 128x128 tile, 8 warps (2m x 4n), k-step 32,
// 3-stage cp.async. smem row stride 24 words (16 data + 8 pad), conflict-free.
#define GRS 24                       // words per row in smem
#define GSTG (128 * GRS)             // per-tensor per-stage words
#define GEMM_SMEM_BYTES (3 * 2 * GSTG * 4)

__global__ __launch_bounds__(256, 2) void gemm_h(const __half* __restrict__ A,
                                                 const __half* __restrict__ B,
                                                 float* __restrict__ C,
                                                 int M, int N, int K) {
    extern __shared__ __align__(16) uint32_t gsm[];
    const int tid = threadIdx.x;
    const int m0 = blockIdx.y * 128;
    const int n0 = blockIdx.x * 128;
    const int warp = tid >> 5;
    const int lane = tid & 31;
    const int gid = lane >> 2;
    const int tig = lane & 3;
    const int wm = (warp & 1) * 64;
    const int wn = (warp >> 1) * 32;

    auto issue = [&](int it) {
        int k0 = it * 32;                       // halves
        uint32_t* As = gsm + (it % 3) * 2 * GSTG;
        uint32_t* Bs = As + GSTG;
#pragma unroll
        for (int i = 0; i < 4; i++) {
            int id = tid + 256 * i;             // 0..1023
            int rid = id & 511;
            int row = rid >> 2, ch = (rid & 3) * 8;   // 8-half chunks
            const __half* src = ((id < 512)
                ? A + (size_t)(m0 + row) * K
                : B + (size_t)(n0 + row) * K) + k0 + ch;
            uint32_t* dst = ((id < 512) ? As : Bs) + row * GRS + (ch >> 1);
            cp16(dst, src);
        }
        asm volatile("cp.async.commit_group;");
    };

    float acc[4][4][4];
#pragma unroll
    for (int mi = 0; mi < 4; mi++)
#pragma unroll
        for (int ni = 0; ni < 4; ni++)
#pragma unroll
            for (int f = 0; f < 4; f++) acc[mi][ni][f] = 0.f;

    const int nIter = K / 32;
    issue(0); issue(1);

    for (int it = 0; it < nIter; it++) {
        asm volatile("cp.async.wait_group 1;");
        __syncthreads();
        if (it + 2 < nIter) issue(it + 2);
        else asm volatile("cp.async.commit_group;");

        const uint32_t* As = gsm + (it % 3) * 2 * GSTG;
        const uint32_t* Bs = As + GSTG;
#pragma unroll
        for (int s = 0; s < 2; s++) {
            uint32_t af[4][4], bf[4][2];
#pragma unroll
            for (int mi = 0; mi < 4; mi++) {
                int r = (wm + 16 * mi + gid) * GRS + 8 * s + 2 * tig;
                uint2 lo = *(const uint2*)&As[r];
                uint2 hi = *(const uint2*)&As[r + 8 * GRS];
                af[mi][0] = lo.x; af[mi][1] = hi.x;
                af[mi][2] = lo.y; af[mi][3] = hi.y;
            }
#pragma unroll
            for (int ni = 0; ni < 4; ni++) {
                uint2 b2 = *(const uint2*)&Bs[(wn + 8 * ni + gid) * GRS + 8 * s + 2 * tig];
                bf[ni][0] = b2.x; bf[ni][1] = b2.y;
            }
#pragma unroll
            for (int mi = 0; mi < 4; mi++)
#pragma unroll
                for (int ni = 0; ni < 4; ni++) mma_f16(acc[mi][ni], af[mi], bf[ni]);
        }
    }

#pragma unroll
    for (int mi = 0; mi < 4; mi++) {
        int r0 = m0 + wm + 16 * mi + gid;
#pragma unroll
        for (int ni = 0; ni < 4; ni++) {
            int c = n0 + wn + 8 * ni + 2 * tig;
            *(float2*)(C + (size_t)r0 * N + c) = make_float2(acc[mi][ni][0], acc[mi][ni][1]);
            *(float2*)(C + (size_t)(r0 + 8) * N + c) = make_float2(acc[mi][ni][2], acc[mi][ni][3]);
        }
    }
}

// ---------------- prep: RMSNorm + RoPE + gain -> half, d word-perm8 --------
__global__ __launch_bounds__(256) void prep_kernel(const float* __restrict__ qkv,
                                                   const float* __restrict__ gain) {
    const int warp = blockIdx.x * 8 + (threadIdx.x >> 5);
    const int lane = threadIdx.x & 31;
    const int NQ = TSEQ * NH;
    const int NK = TSEQ * NKV;
    if (warp >= NQ + NK) return;

    int t, off;
    float g;
    __half* dst;
    if (warp < NQ) {
        t = warp / NH;
        int h = warp % NH;
        off = h * HDIM;
        g = gain[h];
        dst = (__half*)g_q + ((size_t)h * TSEQ + t) * HDIM;
    } else {
        int w = warp - NQ;
        t = w / NKV;
        int kv = w % NKV;
        off = KVOFF + kv * HDIM;
        g = 1.0f;
        dst = (__half*)g_k + ((size_t)kv * TSEQ + t) * HDIM;
    }
    const float* src = qkv + (size_t)t * QKVD + off;
    float x1 = src[lane], x2 = src[lane + 32];
    float ss = x1 * x1 + x2 * x2;
    ss += __shfl_xor_sync(0xffffffffu, ss, 16);
    ss += __shfl_xor_sync(0xffffffffu, ss, 8);
    ss += __shfl_xor_sync(0xffffffffu, ss, 4);
    ss += __shfl_xor_sync(0xffffffffu, ss, 2);
    ss += __shfl_xor_sync(0xffffffffu, ss, 1);
    float r = rsqrtf(ss * (1.0f / 64.0f) + 1.1920929e-07f);
    x1 *= r; x2 *= r;
    float fr = (float)t * g_invf[lane];
    float s, c;
    sincosf(fr, &s, &c);
    int e1 = lane, e2 = lane + 32;
    dst[2 * wp8(e1 >> 1) + (e1 & 1)] = __float2half_rn((x1 * c + x2 * s) * g);
    dst[2 * wp8(e2 >> 1) + (e2 & 1)] = __float2half_rn((x2 * c - x1 * s) * g);
}

// ---------------- V transpose: qkv v-slice -> half [kv][d][t], t perm8 -----
__global__ __launch_bounds__(256) void vtrans_kernel(const float* __restrict__ qkv) {
    __shared__ float ts[32][33];
    const int tx = threadIdx.x & 31;
    const int ty = threadIdx.x >> 5;
    const int t0 = blockIdx.x * 32;
    const int kv = blockIdx.y >> 1;
    const int d0 = (blockIdx.y & 1) * 32;
#pragma unroll
    for (int i = 0; i < 4; i++) {
        int row = ty + 8 * i;
        ts[row][tx] = qkv[(size_t)(t0 + row) * QKVD + VOFF + kv * HDIM + d0 + tx];
    }
    __syncthreads();
    __half* vb = (__half*)g_v + ((size_t)kv * HDIM) * TSEQ;
    int t = t0 + tx;
    int tpos = 2 * wp8(t >> 1) + (t & 1);
#pragma unroll
    for (int i = 0; i < 4; i++) {
        int d = d0 + ty + 8 * i;
        vb[(size_t)d * TSEQ + tpos] = __float2half_rn(ts[tx][ty + 8 * i]);
    }
}

// ---------------- flash attention: fp16 mma, 128-row Q tile, 8 warps -------
// K/Q: rows x 64 halves (d word-perm8); V^T: d-rows x 64 t-halves (t perm8).
// smem stride 40 words/row (32 data + 8 pad) -> conflict-free LDS.64 frags.
// P stays in registers: seq-chunk pairs (2j, 2j+1) form the k16 A-fragment.
#define ASR 40                        // words per row
#define ATILE (64 * ASR)              // words per tile
#define ATTN_SMEM_BYTES (4 * ATILE * 4)

__global__ __launch_bounds__(256, 2) void attn_kernel() {
    extern __shared__ __align__(16) uint32_t smw[];
    uint32_t* Kw = smw;                 // [2][64][40]
    uint32_t* Vw = smw + 2 * ATILE;     // [2][64][40]

    const int tid = threadIdx.x;
    const int h = blockIdx.y;
    const int qb = (int)gridDim.x - 1 - (int)blockIdx.x;  // heavy CTAs first
    const int kvh = h >> 2;
    const int lane = tid & 31;
    const int warp = tid >> 5;
    const int gid = lane >> 2;
    const int tig = lane & 3;
    const int q0w = warp * 16;
    const int kbmax = 2 * qb + 1;

    const __half* kbase = (const __half*)g_k + (size_t)kvh * TSEQ * HDIM;
    const __half* vtbase = (const __half*)g_v + (size_t)kvh * HDIM * TSEQ;

    auto issueKV = [&](int kb) {
        const __half* kp = kbase + (size_t)kb * 64 * HDIM;
        uint32_t* Kd = Kw + (kb & 1) * ATILE;
        uint32_t* Vd = Vw + (kb & 1) * ATILE;
#pragma unroll
        for (int i = 0; i < 4; i++) {
            int slot = tid + 256 * i;           // 0..1023
            int rid = slot & 511;
            int row = rid >> 3, ch = (rid & 7) * 8;   // 8-half chunks
            if (slot < 512)
                cp16(Kd + row * ASR + (ch >> 1), kp + row * HDIM + ch);
            else
                cp16(Vd + row * ASR + (ch >> 1),
                     vtbase + (size_t)row * TSEQ + kb * 64 + ch);
        }
        asm volatile("cp.async.commit_group;");
    };

    // ---- stage Q tile (perm8 halves, verbatim), frags -> registers ----
    {
        const __half* qp = (const __half*)g_q +
                           ((size_t)h * TSEQ + (size_t)qb * 128) * HDIM;
#pragma unroll
        for (int i = 0; i < 4; i++) {
            int slot = tid + 256 * i;           // 0..1023 = 128 rows x 8 chunks
            int row = slot >> 3, ch = (slot & 7) * 8;
            *(float4*)&smw[row * ASR + (ch >> 1)] = *(const float4*)(qp + row * HDIM + ch);
        }
    }
    __syncthreads();
    uint32_t Qf[4][4];
#pragma unroll
    for (int s = 0; s < 4; s++) {
        uint2 lo = *(const uint2*)&smw[(q0w + gid) * ASR + 8 * s + 2 * tig];
        uint2 hi = *(const uint2*)&smw[(q0w + gid + 8) * ASR + 8 * s + 2 * tig];
        Qf[s][0] = lo.x; Qf[s][1] = hi.x; Qf[s][2] = lo.y; Qf[s][3] = hi.y;
    }
    __syncthreads();   // Q frags read; smem now free for K/V

    issueKV(0);

    float of[8][4];
    float s0 = 0.f, s1 = 0.f;
#pragma unroll
    for (int ni = 0; ni < 8; ni++)
#pragma unroll
        for (int f = 0; f < 4; f++) of[ni][f] = 0.f;

    const float cs = 0.18033688011112042f;  // (1/8) * log2(e)
    const int r0g = qb * 128 + q0w + gid;
    const int r1g = r0g + 8;

    for (int kb = 0; kb <= kbmax; kb++) {
        asm volatile("cp.async.wait_group 0;");
        __syncthreads();
        if (kb < kbmax) issueKV(kb + 1);

        const uint32_t* Kc = Kw + (kb & 1) * ATILE;
        const uint32_t* Vc = Vw + (kb & 1) * ATILE;
        const bool diag = (kb >= 2 * qb);

        auto chunk = [&](int ni, float* sf) {
            sf[0] = sf[1] = sf[2] = sf[3] = 0.f;
            const uint32_t* kr = &Kc[(8 * ni + gid) * ASR + 2 * tig];
#pragma unroll
            for (int s = 0; s < 4; s++) {
                uint2 kk = *(const uint2*)&kr[8 * s];
                uint32_t b[2] = {kk.x, kk.y};
                mma_f16(sf, Qf[s], b);
            }
            if (diag) {
                int c0 = kb * 64 + 8 * ni + 2 * tig, c1 = c0 + 1;
                sf[0] = (c0 <= r0g) ? fmaf(sf[0], cs, -8.f) : -INFINITY;
                sf[1] = (c1 <= r0g) ? fmaf(sf[1], cs, -8.f) : -INFINITY;
                sf[2] = (c0 <= r1g) ? fmaf(sf[2], cs, -8.f) : -INFINITY;
                sf[3] = (c1 <= r1g) ? fmaf(sf[3], cs, -8.f) : -INFINITY;
            } else {
                sf[0] = fmaf(sf[0], cs, -8.f);
                sf[1] = fmaf(sf[1], cs, -8.f);
                sf[2] = fmaf(sf[2], cs, -8.f);
                sf[3] = fmaf(sf[3], cs, -8.f);
            }
            sf[0] = ex2(sf[0]); sf[1] = ex2(sf[1]);
            sf[2] = ex2(sf[2]); sf[3] = ex2(sf[3]);
            s0 += sf[0] + sf[1];
            s1 += sf[2] + sf[3];
        };

#pragma unroll
        for (int j = 0; j < 4; j++) {
            float sfa[4], sfb[4];
            chunk(2 * j, sfa);
            chunk(2 * j + 1, sfb);
            uint32_t a[4];
            a[0] = f2h2(sfa[0], sfa[1]);   // row gid,   k = 16j+2tig..+1
            a[1] = f2h2(sfa[2], sfa[3]);   // row gid+8
            a[2] = f2h2(sfb[0], sfb[1]);   // row gid,   k = 16j+8+2tig..+1
            a[3] = f2h2(sfb[2], sfb[3]);   // row gid+8
            const uint32_t* vr = &Vc[gid * ASR + 8 * j + 2 * tig];
#pragma unroll
            for (int ni = 0; ni < 8; ni++) {
                uint2 v2 = *(const uint2*)&vr[8 * ni * ASR];
                uint32_t b[2] = {v2.x, v2.y};
                mma_f16(of[ni], a, b);
            }
        }
    }

    // ---- epilogue: reduce l, normalize, store y half (DIM word-perm8) ----
    s0 += __shfl_xor_sync(0xffffffffu, s0, 1);
    s0 += __shfl_xor_sync(0xffffffffu, s0, 2);
    s1 += __shfl_xor_sync(0xffffffffu, s1, 1);
    s1 += __shfl_xor_sync(0xffffffffu, s1, 2);
    float inv0 = 1.0f / s0, inv1 = 1.0f / s1;
    uint32_t* yw = (uint32_t*)g_y;
#pragma unroll
    for (int ni = 0; ni < 8; ni++) {
        int wpos = wp8(32 * h + 4 * ni + tig);
        yw[(size_t)r0g * 512 + wpos] = f2h2(of[ni][0] * inv0, of[ni][1] * inv0);
        yw[(size_t)r1g * 512 + wpos] = f2h2(of[ni][2] * inv1, of[ni][3] * inv1);
    }
}

// ---------------- launch ---------------------------------------------------
extern "C" void kernel_launch(void* const* d_in, const int* in_sizes, int n_in,
                              void* d_out, int out_size) {
    const float* x      = (const float*)d_in[0];
    const float* w_qkv  = (const float*)d_in[1];
    const float* w_proj = (const float*)d_in[2];
    const float* q_gain = (const float*)d_in[3];
    float* out = (float*)d_out;

    float *qkv_p, *y_p, *xr_p, *wq_p, *wp_p;
    cudaGetSymbolAddress((void**)&qkv_p, g_qkv);
    cudaGetSymbolAddress((void**)&y_p, g_y);
    cudaGetSymbolAddress((void**)&xr_p, g_xr);
    cudaGetSymbolAddress((void**)&wq_p, g_wq);
    cudaGetSymbolAddress((void**)&wp_p, g_wp);

    freq_kernel<<<1, 32>>>();

    round3h_kernel<<<1024, 256>>>(x, (__half*)xr_p, TSEQ * DIM / 4,
                                  w_qkv, (__half*)wq_p, QKVD * DIM / 4,
                                  w_proj, (__half*)wp_p, DIM * DIM / 4);

    cudaFuncSetAttribute(gemm_h, cudaFuncAttributeMaxDynamicSharedMemorySize,
                         GEMM_SMEM_BYTES);
    gemm_h<<<dim3(QKVD / 128, TSEQ / 128), 256, GEMM_SMEM_BYTES>>>(
        (const __half*)xr_p, (const __half*)wq_p, qkv_p, TSEQ, QKVD, DIM);

    {
        int nwarps = TSEQ * (NH + NKV);
        prep_kernel<<<nwarps / 8, 256>>>(qkv_p, q_gain);
    }
    vtrans_kernel<<<dim3(TSEQ / 32, NKV * 2), 256>>>(qkv_p);

    cudaFuncSetAttribute(attn_kernel, cudaFuncAttributeMaxDynamicSharedMemorySize,
                         ATTN_SMEM_BYTES);
    attn_kernel<<<dim3(TSEQ / 128, NH), 256, ATTN_SMEM_BYTES>>>();

    gemm_h<<<dim3(DIM / 128, TSEQ / 128), 256, GEMM_SMEM_BYTES>>>(
        (const __half*)y_p, (const __half*)wp_p, out, TSEQ, DIM, DIM);
}

// round 14
// speedup vs baseline: 6.7774x; 1.0393x over previous
#include <cuda_runtime.h>
#include <cuda_fp16.h>
#include <math.h>
#include <stdint.h>

#define TSEQ 4096
#define NH   16
#define NKV  4
#define HDIM 64
#define DIM  1024
#define QKVD 1536
#define KVOFF 1024
#define VOFF  1280

// ---------------- scratch (device globals; no cudaMalloc allowed) ----------
// float-declared, but several are used as __half (half capacity needed).
__device__ float g_qkv[TSEQ * QKVD];       // f32 (gemm1 output, prep input)
__device__ float g_q[NH * TSEQ * HDIM];    // half, d-axis word-perm8, pre-scaled by gain*cs
__device__ float g_k[NKV * TSEQ * HDIM];   // half, d-axis word-perm8
__device__ float g_v[NKV * TSEQ * HDIM];   // half, TRANSPOSED [kv][d][t], t word-perm8
__device__ float g_y[TSEQ * DIM];          // half, DIM-axis word-perm8
__device__ float g_xr[TSEQ * DIM];         // half, K-axis word-perm8
__device__ float g_wq[QKVD * DIM];         // half, K-axis word-perm8
__device__ float g_wp[DIM * DIM];          // half, K-axis word-perm8
__device__ float g_invf[32];

// ---------------- helpers ---------------------------------------------------
__device__ __forceinline__ uint32_t f2h2(float lo, float hi) {
    __half2 h = __floats2half2_rn(lo, hi);   // .x = lo half
    return *(uint32_t*)&h;
}
__device__ __forceinline__ uint32_t h2ex2(uint32_t x) {
    uint32_t r;
    asm("ex2.approx.f16x2 %0, %1;" : "=r"(r) : "r"(x));
    return r;
}
__device__ __forceinline__ void mma_f16(float c[4], const uint32_t a[4],
                                        const uint32_t b[2]) {
    asm volatile(
        "mma.sync.aligned.m16n8k16.row.col.f32.f16.f16.f32 "
        "{%0,%1,%2,%3}, {%4,%5,%6,%7}, {%8,%9}, {%0,%1,%2,%3};"
        : "+f"(c[0]), "+f"(c[1]), "+f"(c[2]), "+f"(c[3])
        : "r"(a[0]), "r"(a[1]), "r"(a[2]), "r"(a[3]), "r"(b[0]), "r"(b[1]));
}
__device__ __forceinline__ void cp16(void* smem_dst, const void* gsrc) {
    uint32_t s = (uint32_t)__cvta_generic_to_shared(smem_dst);
    asm volatile("cp.async.ca.shared.global [%0], [%1], 16;" :: "r"(s), "l"(gsrc));
}
// word-perm within each 8-word (16-half) block: word w -> 2*(w%4) + (w/4)%2
__device__ __forceinline__ int wp8(int w) {
    return (w & ~7) | ((w & 3) << 1) | ((w >> 2) & 1);
}

// ---------------- one-shot inv_freq ----------------------------------------
__global__ void freq_kernel() {
    int l = threadIdx.x;
    g_invf[l] = (float)(1.0 / pow(10000.0, (double)l * (1.0 / 32.0)));
}

// ---------------- pre-round: f32 -> f16, K-axis word-perm8 -----------------
__global__ __launch_bounds__(256) void round3h_kernel(
    const float* __restrict__ a, __half* __restrict__ da, int n1,
    const float* __restrict__ b, __half* __restrict__ db, int n2,
    const float* __restrict__ c, __half* __restrict__ dc, int n3) {
    int i = blockIdx.x * blockDim.x + threadIdx.x;
    int total = n1 + n2 + n3;
    for (; i < total; i += gridDim.x * blockDim.x) {
        const float* s;
        __half* d;
        int j = i;
        if (j < n1) { s = a; d = da; }
        else if (j < n1 + n2) { j -= n1; s = b; d = db; }
        else { j -= n1 + n2; s = c; d = dc; }
        float4 v = ((const float4*)s)[j];
        uint32_t* du = (uint32_t*)d;
        int w0 = j << 1;
        du[wp8(w0)]     = f2h2(v.x, v.y);
        du[wp8(w0 + 1)] = f2h2(v.z, v.w);
    }
}

// ---------------- fp16 GEMM: C[M,N] = A[M,K] * B[N,K]^T --------------------
// A,B half, K-axis word-perm8. 128x128 tile, 8 warps (2m x 4n), k-step 32,
// 3-stage cp.async. smem row stride 24 words (16 data + 8 pad), conflict-free.
#define GRS 24                       // words per row in smem
#define GSTG (128 * GRS)             // per-tensor per-stage words
#define GEMM_SMEM_BYTES (3 * 2 * GSTG * 4)

__global__ __launch_bounds__(256, 2) void gemm_h(const __half* __restrict__ A,
                                                 const __half* __restrict__ B,
                                                 float* __restrict__ C,
                                                 int M, int N, int K) {
    extern __shared__ __align__(16) uint32_t gsm[];
    const int tid = threadIdx.x;
    const int m0 = blockIdx.y * 128;
    const int n0 = blockIdx.x * 128;
    const int warp = tid >> 5;
    const int lane = tid & 31;
    const int gid = lane >> 2;
    const int tig = lane & 3;
    const int wm = (warp & 1) * 64;
    const int wn = (warp >> 1) * 32;

    auto issue = [&](int it) {
        int k0 = it * 32;                       // halves
        uint32_t* As = gsm + (it % 3) * 2 * GSTG;
        uint32_t* Bs = As + GSTG;
#pragma unroll
        for (int i = 0; i < 4; i++) {
            int id = tid + 256 * i;             // 0..1023
            int rid = id & 511;
            int row = rid >> 2, ch = (rid & 3) * 8;   // 8-half chunks
            const __half* src = ((id < 512)
                ? A + (size_t)(m0 + row) * K
                : B + (size_t)(n0 + row) * K) + k0 + ch;
            uint32_t* dst = ((id < 512) ? As : Bs) + row * GRS + (ch >> 1);
            cp16(dst, src);
        }
        asm volatile("cp.async.commit_group;");
    };

    float acc[4][4][4];
#pragma unroll
    for (int mi = 0; mi < 4; mi++)
#pragma unroll
        for (int ni = 0; ni < 4; ni++)
#pragma unroll
            for (int f = 0; f < 4; f++) acc[mi][ni][f] = 0.f;

    const int nIter = K / 32;
    issue(0); issue(1);

    for (int it = 0; it < nIter; it++) {
        asm volatile("cp.async.wait_group 1;");
        __syncthreads();
        if (it + 2 < nIter) issue(it + 2);
        else asm volatile("cp.async.commit_group;");

        const uint32_t* As = gsm + (it % 3) * 2 * GSTG;
        const uint32_t* Bs = As + GSTG;
#pragma unroll
        for (int s = 0; s < 2; s++) {
            uint32_t af[4][4], bf[4][2];
#pragma unroll
            for (int mi = 0; mi < 4; mi++) {
                int r = (wm + 16 * mi + gid) * GRS + 8 * s + 2 * tig;
                uint2 lo = *(const uint2*)&As[r];
                uint2 hi = *(const uint2*)&As[r + 8 * GRS];
                af[mi][0] = lo.x; af[mi][1] = hi.x;
                af[mi][2] = lo.y; af[mi][3] = hi.y;
            }
#pragma unroll
            for (int ni = 0; ni < 4; ni++) {
                uint2 b2 = *(const uint2*)&Bs[(wn + 8 * ni + gid) * GRS + 8 * s + 2 * tig];
                bf[ni][0] = b2.x; bf[ni][1] = b2.y;
            }
#pragma unroll
            for (int mi = 0; mi < 4; mi++)
#pragma unroll
                for (int ni = 0; ni < 4; ni++) mma_f16(acc[mi][ni], af[mi], bf[ni]);
        }
    }

#pragma unroll
    for (int mi = 0; mi < 4; mi++) {
        int r0 = m0 + wm + 16 * mi + gid;
#pragma unroll
        for (int ni = 0; ni < 4; ni++) {
            int c = n0 + wn + 8 * ni + 2 * tig;
            *(float2*)(C + (size_t)r0 * N + c) = make_float2(acc[mi][ni][0], acc[mi][ni][1]);
            *(float2*)(C + (size_t)(r0 + 8) * N + c) = make_float2(acc[mi][ni][2], acc[mi][ni][3]);
        }
    }
}

// ---------------- prep: RMSNorm + RoPE + gain -> half, d word-perm8 --------
// Q is additionally pre-scaled by cs = (1/8)*log2(e), so the attention S-mma
// directly produces log2-domain scores.
__global__ __launch_bounds__(256) void prep_kernel(const float* __restrict__ qkv,
                                                   const float* __restrict__ gain) {
    const int warp = blockIdx.x * 8 + (threadIdx.x >> 5);
    const int lane = threadIdx.x & 31;
    const int NQ = TSEQ * NH;
    const int NK = TSEQ * NKV;
    if (warp >= NQ + NK) return;

    const float cs = 0.18033688011112042f;
    int t, off;
    float g;
    __half* dst;
    if (warp < NQ) {
        t = warp / NH;
        int h = warp % NH;
        off = h * HDIM;
        g = gain[h] * cs;
        dst = (__half*)g_q + ((size_t)h * TSEQ + t) * HDIM;
    } else {
        int w = warp - NQ;
        t = w / NKV;
        int kv = w % NKV;
        off = KVOFF + kv * HDIM;
        g = 1.0f;
        dst = (__half*)g_k + ((size_t)kv * TSEQ + t) * HDIM;
    }
    const float* src = qkv + (size_t)t * QKVD + off;
    float x1 = src[lane], x2 = src[lane + 32];
    float ss = x1 * x1 + x2 * x2;
    ss += __shfl_xor_sync(0xffffffffu, ss, 16);
    ss += __shfl_xor_sync(0xffffffffu, ss, 8);
    ss += __shfl_xor_sync(0xffffffffu, ss, 4);
    ss += __shfl_xor_sync(0xffffffffu, ss, 2);
    ss += __shfl_xor_sync(0xffffffffu, ss, 1);
    float r = rsqrtf(ss * (1.0f / 64.0f) + 1.1920929e-07f);
    x1 *= r; x2 *= r;
    float fr = (float)t * g_invf[lane];
    float s, c;
    sincosf(fr, &s, &c);
    int e1 = lane, e2 = lane + 32;
    dst[2 * wp8(e1 >> 1) + (e1 & 1)] = __float2half_rn((x1 * c + x2 * s) * g);
    dst[2 * wp8(e2 >> 1) + (e2 & 1)] = __float2half_rn((x2 * c - x1 * s) * g);
}

// ---------------- V transpose: qkv v-slice -> half [kv][d][t], t perm8 -----
__global__ __launch_bounds__(256) void vtrans_kernel(const float* __restrict__ qkv) {
    __shared__ float ts[32][33];
    const int tx = threadIdx.x & 31;
    const int ty = threadIdx.x >> 5;
    const int t0 = blockIdx.x * 32;
    const int kv = blockIdx.y >> 1;
    const int d0 = (blockIdx.y & 1) * 32;
#pragma unroll
    for (int i = 0; i < 4; i++) {
        int row = ty + 8 * i;
        ts[row][tx] = qkv[(size_t)(t0 + row) * QKVD + VOFF + kv * HDIM + d0 + tx];
    }
    __syncthreads();
    __half* vb = (__half*)g_v + ((size_t)kv * HDIM) * TSEQ;
    int t = t0 + tx;
    int tpos = 2 * wp8(t >> 1) + (t & 1);
#pragma unroll
    for (int i = 0; i < 4; i++) {
        int d = d0 + ty + 8 * i;
        vb[(size_t)d * TSEQ + tpos] = __float2half_rn(ts[tx][ty + 8 * i]);
    }
}

// ---------------- flash attention: fp16 mma, 128-row Q tile, 8 warps -------
// Q pre-scaled by cs -> S is directly log2-domain. No bias (2^s cancels in
// O/l; P <= 2^11.54 < half max). P = ex2.approx.f16x2 of packed S pairs.
// l computed by a ones-column mma on the SAME half P fragments (exact f32
// row sums, no shfl reduction needed). P never touches smem.
#define ASR 40                        // words per row
#define ATILE (64 * ASR)              // words per tile
#define ATTN_SMEM_BYTES (4 * ATILE * 4)

__global__ __launch_bounds__(256, 2) void attn_kernel() {
    extern __shared__ __align__(16) uint32_t smw[];
    uint32_t* Kw = smw;                 // [2][64][40]
    uint32_t* Vw = smw + 2 * ATILE;     // [2][64][40]

    const int tid = threadIdx.x;
    const int h = blockIdx.y;
    const int qb = (int)gridDim.x - 1 - (int)blockIdx.x;  // heavy CTAs first
    const int kvh = h >> 2;
    const int lane = tid & 31;
    const int warp = tid >> 5;
    const int gid = lane >> 2;
    const int tig = lane & 3;
    const int q0w = warp * 16;
    const int kbmax = 2 * qb + 1;

    const __half* kbase = (const __half*)g_k + (size_t)kvh * TSEQ * HDIM;
    const __half* vtbase = (const __half*)g_v + (size_t)kvh * HDIM * TSEQ;

    auto issueKV = [&](int kb) {
        const __half* kp = kbase + (size_t)kb * 64 * HDIM;
        uint32_t* Kd = Kw + (kb & 1) * ATILE;
        uint32_t* Vd = Vw + (kb & 1) * ATILE;
#pragma unroll
        for (int i = 0; i < 4; i++) {
            int slot = tid + 256 * i;           // 0..1023
            int rid = slot & 511;
            int row = rid >> 3, ch = (rid & 7) * 8;   // 8-half chunks
            if (slot < 512)
                cp16(Kd + row * ASR + (ch >> 1), kp + row * HDIM + ch);
            else
                cp16(Vd + row * ASR + (ch >> 1),
                     vtbase + (size_t)row * TSEQ + kb * 64 + ch);
        }
        asm volatile("cp.async.commit_group;");
    };

    // ---- stage Q tile (perm8 halves, verbatim), frags -> registers ----
    {
        const __half* qp = (const __half*)g_q +
                           ((size_t)h * TSEQ + (size_t)qb * 128) * HDIM;
#pragma unroll
        for (int i = 0; i < 4; i++) {
            int slot = tid + 256 * i;           // 0..1023 = 128 rows x 8 chunks
            int row = slot >> 3, ch = (slot & 7) * 8;
            *(float4*)&smw[row * ASR + (ch >> 1)] = *(const float4*)(qp + row * HDIM + ch);
        }
    }
    __syncthreads();
    uint32_t Qf[4][4];
#pragma unroll
    for (int s = 0; s < 4; s++) {
        uint2 lo = *(const uint2*)&smw[(q0w + gid) * ASR + 8 * s + 2 * tig];
        uint2 hi = *(const uint2*)&smw[(q0w + gid + 8) * ASR + 8 * s + 2 * tig];
        Qf[s][0] = lo.x; Qf[s][1] = hi.x; Qf[s][2] = lo.y; Qf[s][3] = hi.y;
    }
    __syncthreads();   // Q frags read; smem now free for K/V

    issueKV(0);

    float of[8][4];
    float lacc[4] = {0.f, 0.f, 0.f, 0.f};
#pragma unroll
    for (int ni = 0; ni < 8; ni++)
#pragma unroll
        for (int f = 0; f < 4; f++) of[ni][f] = 0.f;

    const uint32_t ones2 = 0x3C003C00u;   // half2 {1, 1}
    const int r0g = qb * 128 + q0w + gid;
    const int r1g = r0g + 8;

    for (int kb = 0; kb <= kbmax; kb++) {
        asm volatile("cp.async.wait_group 0;");
        __syncthreads();
        if (kb < kbmax) issueKV(kb + 1);

        const uint32_t* Kc = Kw + (kb & 1) * ATILE;
        const uint32_t* Vc = Vw + (kb & 1) * ATILE;
        const bool diag = (kb >= 2 * qb);

        // S chunk (8 seq cols) in log2 domain (Q pre-scaled); mask only on diag
        auto chunk = [&](int ni, float* sf) {
            sf[0] = sf[1] = sf[2] = sf[3] = 0.f;
            const uint32_t* kr = &Kc[(8 * ni + gid) * ASR + 2 * tig];
#pragma unroll
            for (int s = 0; s < 4; s++) {
                uint2 kk = *(const uint2*)&kr[8 * s];
                uint32_t b[2] = {kk.x, kk.y};
                mma_f16(sf, Qf[s], b);
            }
            if (diag) {
                int c0 = kb * 64 + 8 * ni + 2 * tig, c1 = c0 + 1;
                sf[0] = (c0 <= r0g) ? sf[0] : -INFINITY;
                sf[1] = (c1 <= r0g) ? sf[1] : -INFINITY;
                sf[2] = (c0 <= r1g) ? sf[2] : -INFINITY;
                sf[3] = (c1 <= r1g) ? sf[3] : -INFINITY;
            }
        };

#pragma unroll
        for (int j = 0; j < 4; j++) {
            float sfa[4], sfb[4];
            chunk(2 * j, sfa);
            chunk(2 * j + 1, sfb);
            // P = 2^S computed pairwise in half domain
            uint32_t a[4];
            a[0] = h2ex2(f2h2(sfa[0], sfa[1]));   // row gid,   k = 16j+2tig..+1
            a[1] = h2ex2(f2h2(sfa[2], sfa[3]));   // row gid+8
            a[2] = h2ex2(f2h2(sfb[0], sfb[1]));   // row gid,   k = 16j+8+..
            a[3] = h2ex2(f2h2(sfb[2], sfb[3]));   // row gid+8
            // l += row-sums of P (exact f32, same halves as PV)
            {
                uint32_t b[2] = {ones2, ones2};
                mma_f16(lacc, a, b);
            }
            const uint32_t* vr = &Vc[gid * ASR + 8 * j + 2 * tig];
#pragma unroll
            for (int ni = 0; ni < 8; ni++) {
                uint2 v2 = *(const uint2*)&vr[8 * ni * ASR];
                uint32_t b[2] = {v2.x, v2.y};
                mma_f16(of[ni], a, b);
            }
        }
    }

    // ---- epilogue: normalize by l (already complete per lane), store y ----
    float inv0 = 1.0f / lacc[0], inv1 = 1.0f / lacc[2];
    uint32_t* yw = (uint32_t*)g_y;
#pragma unroll
    for (int ni = 0; ni < 8; ni++) {
        int wpos = wp8(32 * h + 4 * ni + tig);
        yw[(size_t)r0g * 512 + wpos] = f2h2(of[ni][0] * inv0, of[ni][1] * inv0);
        yw[(size_t)r1g * 512 + wpos] = f2h2(of[ni][2] * inv1, of[ni][3] * inv1);
    }
}

// ---------------- launch ---------------------------------------------------
extern "C" void kernel_launch(void* const* d_in, const int* in_sizes, int n_in,
                              void* d_out, int out_size) {
    const float* x      = (const float*)d_in[0];
    const float* w_qkv  = (const float*)d_in[1];
    const float* w_proj = (const float*)d_in[2];
    const float* q_gain = (const float*)d_in[3];
    float* out = (float*)d_out;

    float *qkv_p, *y_p, *xr_p, *wq_p, *wp_p;
    cudaGetSymbolAddress((void**)&qkv_p, g_qkv);
    cudaGetSymbolAddress((void**)&y_p, g_y);
    cudaGetSymbolAddress((void**)&xr_p, g_xr);
    cudaGetSymbolAddress((void**)&wq_p, g_wq);
    cudaGetSymbolAddress((void**)&wp_p, g_wp);

    freq_kernel<<<1, 32>>>();

    round3h_kernel<<<1024, 256>>>(x, (__half*)xr_p, TSEQ * DIM / 4,
                                  w_qkv, (__half*)wq_p, QKVD * DIM / 4,
                                  w_proj, (__half*)wp_p, DIM * DIM / 4);

    cudaFuncSetAttribute(gemm_h, cudaFuncAttributeMaxDynamicSharedMemorySize,
                         GEMM_SMEM_BYTES);
    gemm_h<<<dim3(QKVD / 128, TSEQ / 128), 256, GEMM_SMEM_BYTES>>>(
        (const __half*)xr_p, (const __half*)wq_p, qkv_p, TSEQ, QKVD, DIM);

    {
        int nwarps = TSEQ * (NH + NKV);
        prep_kernel<<<nwarps / 8, 256>>>(qkv_p, q_gain);
    }
    vtrans_kernel<<<dim3(TSEQ / 32, NKV * 2), 256>>>(qkv_p);

    cudaFuncSetAttribute(attn_kernel, cudaFuncAttributeMaxDynamicSharedMemorySize,
                         ATTN_SMEM_BYTES);
    attn_kernel<<<dim3(TSEQ / 128, NH), 256, ATTN_SMEM_BYTES>>>();

    gemm_h<<<dim3(DIM / 128, TSEQ / 128), 256, GEMM_SMEM_BYTES>>>(
        (const __half*)y_p, (const __half*)wp_p, out, TSEQ, DIM, DIM);
}